// round 14
// baseline (speedup 1.0000x reference)
#include <cuda_runtime.h>
#include <cuda_bf16.h>
#include <cuda_fp16.h>
#include <cstdint>

// Problem constants
#define BATCH 2
#define SEQL  2048
#define DMODEL 1024
#define NHEAD 16
#define DHEAD 64
#define BLROWS (BATCH * SEQL)   // 4096
#define GK 1024

// ---------------------------------------------------------------------------
// Scratch
// ---------------------------------------------------------------------------
__device__ __half g_in3hi[(size_t)3 * BLROWS * DMODEL];                 // q,k,v split (fp16)
__device__ __half g_in3lo[(size_t)3 * BLROWS * DMODEL];
__device__ __half g_w4hi[(size_t)4 * DMODEL * DMODEL];                  // W^T rounded fp16
__device__ __nv_bfloat16 g_qhi[(size_t)BLROWS * DMODEL];
__device__ __nv_bfloat16 g_qlo[(size_t)BLROWS * DMODEL];
__device__ __nv_bfloat16 g_khi[(size_t)BLROWS * DMODEL];
__device__ __nv_bfloat16 g_klo[(size_t)BLROWS * DMODEL];
__device__ __nv_bfloat16 g_vhi[(size_t)BLROWS * DMODEL];                // V proj, token-major
__device__ __nv_bfloat16 g_vlo[(size_t)BLROWS * DMODEL];
__device__ __half g_atthi[(size_t)BLROWS * DMODEL];                     // attention out (fp16 split)
__device__ __half g_attlo[(size_t)BLROWS * DMODEL];

// ---------------------------------------------------------------------------
// PTX helpers
// ---------------------------------------------------------------------------
__device__ __forceinline__ uint32_t s2u(const void* p) {
    uint32_t a;
    asm("{ .reg .u64 t; cvta.to.shared.u64 t, %1; cvt.u32.u64 %0, t; }"
        : "=r"(a) : "l"(p));
    return a;
}
__device__ __forceinline__ void ldsm_x4(uint32_t* r, uint32_t addr) {
    asm volatile("ldmatrix.sync.aligned.m8n8.x4.shared.b16 {%0,%1,%2,%3}, [%4];"
                 : "=r"(r[0]), "=r"(r[1]), "=r"(r[2]), "=r"(r[3]) : "r"(addr));
}
__device__ __forceinline__ void ldsm_x4t(uint32_t* r, uint32_t addr) {
    asm volatile("ldmatrix.sync.aligned.m8n8.x4.trans.shared.b16 {%0,%1,%2,%3}, [%4];"
                 : "=r"(r[0]), "=r"(r[1]), "=r"(r[2]), "=r"(r[3]) : "r"(addr));
}
// bf16 mma (attention)
__device__ __forceinline__ void mma_bf16(float* d, const uint32_t* a, const uint32_t* b) {
    asm volatile("mma.sync.aligned.m16n8k16.row.col.f32.bf16.bf16.f32 "
                 "{%0,%1,%2,%3}, {%4,%5,%6,%7}, {%8,%9}, {%0,%1,%2,%3};"
                 : "+f"(d[0]), "+f"(d[1]), "+f"(d[2]), "+f"(d[3])
                 : "r"(a[0]), "r"(a[1]), "r"(a[2]), "r"(a[3]), "r"(b[0]), "r"(b[1]));
}
// fp16 mma (projection GEMMs)
__device__ __forceinline__ void mma_f16(float* d, const uint32_t* a, const uint32_t* b) {
    asm volatile("mma.sync.aligned.m16n8k16.row.col.f32.f16.f16.f32 "
                 "{%0,%1,%2,%3}, {%4,%5,%6,%7}, {%8,%9}, {%0,%1,%2,%3};"
                 : "+f"(d[0]), "+f"(d[1]), "+f"(d[2]), "+f"(d[3])
                 : "r"(a[0]), "r"(a[1]), "r"(a[2]), "r"(a[3]), "r"(b[0]), "r"(b[1]));
}
__device__ __forceinline__ void cpa16(uint32_t saddr, const void* g) {
    asm volatile("cp.async.cg.shared.global [%0], [%1], 16;" :: "r"(saddr), "l"(g));
}
#define CP_COMMIT() asm volatile("cp.async.commit_group;" ::: "memory")
#define CP_WAIT1()  asm volatile("cp.async.wait_group 1;" ::: "memory")
#define CP_WAIT0()  asm volatile("cp.async.wait_group 0;" ::: "memory")

__device__ __forceinline__ uint32_t packbf(float lo, float hi) {
    uint32_t d;
    asm("cvt.rn.bf16x2.f32 %0, %1, %2;" : "=r"(d) : "f"(hi), "f"(lo));
    return d;
}

// ---------------------------------------------------------------------------
// Conversion kernels
// ---------------------------------------------------------------------------
// q,k,v fp32 -> fp16 hi/lo (exact split). 4 coalesced float4 per thread.
__global__ __launch_bounds__(256) void split3(const float* __restrict__ q,
                                              const float* __restrict__ k,
                                              const float* __restrict__ v,
                                              __half* __restrict__ hi,
                                              __half* __restrict__ lo,
                                              int n4) {
    const int base = blockIdx.x * 1024 + threadIdx.x;
    const int z = blockIdx.z;
    const float* in = (z == 0) ? q : (z == 1) ? k : v;
    const size_t off = (size_t)z * BLROWS * DMODEL / 2;   // half2 units
    float4 val[4];
#pragma unroll
    for (int t = 0; t < 4; t++) {
        int i = base + t * 256;
        if (i < n4) val[t] = ((const float4*)in)[i];
    }
#pragma unroll
    for (int t = 0; t < 4; t++) {
        const int i = base + t * 256;
        if (i < n4) {
            __half h0 = __float2half(val[t].x);
            __half h1 = __float2half(val[t].y);
            __half h2 = __float2half(val[t].z);
            __half h3 = __float2half(val[t].w);
            __half l0 = __float2half(val[t].x - __half2float(h0));
            __half l1 = __float2half(val[t].y - __half2float(h1));
            __half l2 = __float2half(val[t].z - __half2float(h2));
            __half l3 = __float2half(val[t].w - __half2float(h3));
            ((__half2*)hi)[off + 2 * i]     = __halves2half2(h0, h1);
            ((__half2*)hi)[off + 2 * i + 1] = __halves2half2(h2, h3);
            ((__half2*)lo)[off + 2 * i]     = __halves2half2(l0, l1);
            ((__half2*)lo)[off + 2 * i + 1] = __halves2half2(l2, l3);
        }
    }
}

// W [K][N] fp32 -> Wt [N][K] fp16 (transposed, rounded), all four weights.
__global__ __launch_bounds__(256) void splitT4(const float* __restrict__ w0,
                                               const float* __restrict__ w1,
                                               const float* __restrict__ w2,
                                               const float* __restrict__ w3,
                                               __half* __restrict__ th) {
    __shared__ float t[32][33];
    const int tx = threadIdx.x, ty = threadIdx.y;
    const int n0 = blockIdx.x * 32, k0 = blockIdx.y * 32;
    const int z = blockIdx.z;
    const float* W = (z == 0) ? w0 : (z == 1) ? w1 : (z == 2) ? w2 : w3;
    const size_t zoff = (size_t)z * DMODEL * DMODEL;
#pragma unroll
    for (int i = 0; i < 32; i += 8)
        t[ty + i][tx] = W[(size_t)(k0 + ty + i) * DMODEL + n0 + tx];
    __syncthreads();
#pragma unroll
    for (int i = 0; i < 32; i += 8) {
        float x = t[tx][ty + i];
        th[zoff + (size_t)(n0 + ty + i) * DMODEL + k0 + tx] = __float2half(x);
    }
}

// ---------------------------------------------------------------------------
// fp16 2-pass GEMM: C = (A_hi + A_lo) @ B_hi   (= A @ fp16(W), error ~2^-12)
// 128x128 block, 4 warps (64x64 warp tiles), 3-stage pipeline, K-chunk 32.
// ---------------------------------------------------------------------------
#define GBUF   8192u                 // one 128x32 fp16 tile
#define GSTG   24576u                // 3 tiles per stage
#define SMEM_GEMM (3u * GSTG)        // 73728
#define GEMM_THREADS 128

__device__ __forceinline__ void stage_load32(const __half* __restrict__ Ahi,
                                             const __half* __restrict__ Alo,
                                             const __half* __restrict__ B,
                                             int am0, int bn0, int k0,
                                             uint32_t sbase, int tid) {
#pragma unroll
    for (int b = 0; b < 3; b++) {
        const __half* g = (b == 0) ? Ahi : (b == 1) ? Alo : B;
        const int r0 = (b < 2) ? am0 : bn0;
        const uint32_t sbuf = sbase + b * GBUF;
#pragma unroll
        for (int t = 0; t < 4; t++) {
            int u = tid + t * GEMM_THREADS;
            int row = u >> 2, c = u & 3;
            int sw = c ^ ((row >> 1) & 3);
            cpa16(sbuf + row * 64 + sw * 16,
                  g + (size_t)(r0 + row) * GK + k0 + c * 8);
        }
    }
}

__device__ __forceinline__ void gemm_body(const __half* __restrict__ Ahi,
                                          const __half* __restrict__ Alo,
                                          const __half* __restrict__ B,
                                          float* __restrict__ C,
                                          __nv_bfloat16* __restrict__ Chi,
                                          __nv_bfloat16* __restrict__ Clo,
                                          int N, bool bfout, uint32_t sb,
                                          int bm, int bn) {
    const int tid = threadIdx.x;
    const int wid = tid >> 5, lane = tid & 31;
    const int wm = wid & 1;          // 64-row slab
    const int wn = wid >> 1;         // 64-col slab
    const int am0 = bm * 128, bn0 = bn * 128;

    float acc[4][8][4];
#pragma unroll
    for (int i = 0; i < 4; i++)
#pragma unroll
        for (int j = 0; j < 8; j++)
#pragma unroll
            for (int r = 0; r < 4; r++) acc[i][j][r] = 0.f;

    const int NC = GK / 32;          // 32 chunks
    stage_load32(Ahi, Alo, B, am0, bn0, 0, sb, tid);
    CP_COMMIT();
    stage_load32(Ahi, Alo, B, am0, bn0, 32, sb + GSTG, tid);
    CP_COMMIT();

    const int ra = lane & 15, ca = lane >> 4;
    const int jb_off = (lane >> 4) & 1;
    const int kb_half = (lane >> 3) & 1;
    const int rb = lane & 7;
    int stg = 0;
    for (int c = 0; c < NC; c++) {
        if (c < NC - 1) CP_WAIT1(); else CP_WAIT0();
        __syncthreads();

        const uint32_t base = sb + stg * GSTG;
#pragma unroll
        for (int ks = 0; ks < 2; ks++) {
            uint32_t ah[4][4], al[4][4];
#pragma unroll
            for (int i = 0; i < 4; i++) {
                int row = wm * 64 + i * 16 + ra;
                int ch = (ks * 2 + ca) ^ ((row >> 1) & 3);
                uint32_t ad = base + row * 64 + ch * 16;
                ldsm_x4(ah[i], ad);
                ldsm_x4(al[i], ad + GBUF);
            }
            uint32_t bh[8][2];
#pragma unroll
            for (int jp = 0; jp < 4; jp++) {
                int row = wn * 64 + (jp * 2 + jb_off) * 8 + rb;
                int ch = (ks * 2 + kb_half) ^ ((row >> 1) & 3);
                uint32_t bd = base + 2 * GBUF + row * 64 + ch * 16;
                ldsm_x4(bh[jp * 2], bd);
            }
#pragma unroll
            for (int i = 0; i < 4; i++)
#pragma unroll
                for (int j = 0; j < 8; j++)
                    mma_f16(acc[i][j], ah[i], bh[j]);
#pragma unroll
            for (int i = 0; i < 4; i++)
#pragma unroll
                for (int j = 0; j < 8; j++)
                    mma_f16(acc[i][j], al[i], bh[j]);
        }

        if (c + 2 < NC) {
            stage_load32(Ahi, Alo, B, am0, bn0, (c + 2) * 32,
                         sb + ((stg + 2) % 3) * GSTG, tid);
            CP_COMMIT();
        }
        stg = (stg + 1) % 3;
    }

    const int r0 = lane >> 2, c0 = (lane & 3) * 2;
#pragma unroll
    for (int i = 0; i < 4; i++) {
#pragma unroll
        for (int j = 0; j < 8; j++) {
            const int grow = am0 + wm * 64 + i * 16 + r0;
            const int gcol = bn0 + wn * 64 + j * 8 + c0;
            if (!bfout) {
                float2 v0 = {acc[i][j][0], acc[i][j][1]};
                float2 v1 = {acc[i][j][2], acc[i][j][3]};
                *(float2*)(C + (size_t)grow * N + gcol)       = v0;
                *(float2*)(C + (size_t)(grow + 8) * N + gcol) = v1;
            } else {
#pragma unroll
                for (int half = 0; half < 2; half++) {
                    float a0 = acc[i][j][half * 2], a1 = acc[i][j][half * 2 + 1];
                    float h0 = __bfloat162float(__float2bfloat16(a0));
                    float h1 = __bfloat162float(__float2bfloat16(a1));
                    size_t o = (size_t)(grow + half * 8) * N + gcol;
                    *(uint32_t*)(Chi + o) = packbf(h0, h1);
                    *(uint32_t*)(Clo + o) = packbf(a0 - h0, a1 - h1);
                }
            }
        }
    }
}

// Fused Q/K/V projections: grid (8, 32, 3), all write bf16 hi/lo token-major.
__global__ __launch_bounds__(GEMM_THREADS, 2) void gemm_qkv(const __half* __restrict__ i3h,
                                                            const __half* __restrict__ i3l,
                                                            const __half* __restrict__ w4h,
                                                            __nv_bfloat16* __restrict__ qhi,
                                                            __nv_bfloat16* __restrict__ qlo,
                                                            __nv_bfloat16* __restrict__ khi,
                                                            __nv_bfloat16* __restrict__ klo,
                                                            __nv_bfloat16* __restrict__ vhi,
                                                            __nv_bfloat16* __restrict__ vlo) {
    extern __shared__ char sm[];
    const uint32_t sb = s2u(sm);
    const int z = blockIdx.z;
    const size_t IS = (size_t)BLROWS * DMODEL;
    const size_t WS = (size_t)DMODEL * DMODEL;
    __nv_bfloat16* Chi = (z == 0) ? qhi : (z == 1) ? khi : vhi;
    __nv_bfloat16* Clo = (z == 0) ? qlo : (z == 1) ? klo : vlo;
    gemm_body(i3h + (size_t)z * IS, i3l + (size_t)z * IS, w4h + (size_t)z * WS,
              nullptr, Chi, Clo, DMODEL, true, sb, blockIdx.y, blockIdx.x);
}

// Wo projection, fp32 out
__global__ __launch_bounds__(GEMM_THREADS, 2) void gemm_wo(const __half* __restrict__ Ahi,
                                                           const __half* __restrict__ Alo,
                                                           const __half* __restrict__ B,
                                                           float* __restrict__ C) {
    extern __shared__ char sm[];
    const uint32_t sb = s2u(sm);
    gemm_body(Ahi, Alo, B, C, nullptr, nullptr, DMODEL, false, sb,
              blockIdx.y, blockIdx.x);
}

// ---------------------------------------------------------------------------
// Tensor-core causal flash attention (bf16 3-pass internals).
// K and V both token-major; V B-fragments via ldmatrix.trans.
// ---------------------------------------------------------------------------
#define AT_Q    0u
#define AT_STG0 32768u
#define AT_STGB 32768u
#define SMEM_ATT 98304u

__device__ __forceinline__ void att_load_kv(const __nv_bfloat16* __restrict__ Khi,
                                            const __nv_bfloat16* __restrict__ Klo,
                                            const __nv_bfloat16* __restrict__ Vhi,
                                            const __nv_bfloat16* __restrict__ Vlo,
                                            int b, int h, int kb,
                                            uint32_t stg, int tid) {
    const size_t gb = (size_t)(b * SEQL + kb * 64) * DMODEL + h * DHEAD;
#pragma unroll
    for (int t = 0; t < 2; t++) {
        int u = tid + t * 256;
        int row = u >> 3, c = u & 7;
        uint32_t soff = row * 128 + ((c ^ (row & 7)) * 16);
        const size_t goff = gb + (size_t)row * DMODEL + c * 8;
        cpa16(stg + soff,          Khi + goff);
        cpa16(stg + 8192 + soff,   Klo + goff);
        cpa16(stg + 16384 + soff,  Vhi + goff);
        cpa16(stg + 24576 + soff,  Vlo + goff);
    }
}

__global__ __launch_bounds__(256, 2) void attn_tc(const __nv_bfloat16* __restrict__ Qhi,
                                                  const __nv_bfloat16* __restrict__ Qlo,
                                                  const __nv_bfloat16* __restrict__ Khi,
                                                  const __nv_bfloat16* __restrict__ Klo,
                                                  const __nv_bfloat16* __restrict__ Vhi,
                                                  const __nv_bfloat16* __restrict__ Vlo,
                                                  __half* __restrict__ Ohi,
                                                  __half* __restrict__ Olo) {
    extern __shared__ char sm[];
    const uint32_t sb = s2u(sm);
    const int tid = threadIdx.x;
    const int wid = tid >> 5, lane = tid & 31;
    const int qb = (int)gridDim.y - 1 - (int)blockIdx.y;   // heavy tiles first
    const int h = blockIdx.x & 15, b = blockIdx.x >> 4;

    {
        const size_t qgb = (size_t)(b * SEQL + qb * 128) * DMODEL + h * DHEAD;
#pragma unroll
        for (int t = 0; t < 4; t++) {
            int u = tid + t * 256;
            int row = u >> 3, c = u & 7;
            uint32_t soff = row * 128 + ((c ^ (row & 7)) * 16);
            cpa16(sb + AT_Q + soff,         Qhi + qgb + (size_t)row * DMODEL + c * 8);
            cpa16(sb + AT_Q + 16384 + soff, Qlo + qgb + (size_t)row * DMODEL + c * 8);
        }
    }
    CP_COMMIT();

    float o[8][4];
#pragma unroll
    for (int nt = 0; nt < 8; nt++)
#pragma unroll
        for (int r = 0; r < 4; r++) o[nt][r] = 0.f;
    float m[2] = {-1e30f, -1e30f};
    float l[2] = {0.f, 0.f};

    const int qw = qb * 128 + wid * 16;
    const int r0 = lane >> 2, c0 = (lane & 3) * 2;
    const int ra = lane & 15, ca = lane >> 4;
    const int jb_off = (lane >> 4) & 1;      // which tile of the ldsm_x4 pair
    const int kb_half = (lane >> 3) & 1;     // k-half within the pair
    const int rb = lane & 7;
    const int last = 2 * qb + 1;

    att_load_kv(Khi, Klo, Vhi, Vlo, b, h, 0, sb + AT_STG0, tid);
    CP_COMMIT();

    for (int kb = 0; kb <= last; kb++) {
        if (kb < last) {
            att_load_kv(Khi, Klo, Vhi, Vlo, b, h, kb + 1,
                        sb + AT_STG0 + ((kb + 1) & 1) * AT_STGB, tid);
            CP_COMMIT();
            CP_WAIT1();
        } else {
            CP_WAIT0();
        }
        __syncthreads();

        const int avail = qw + 15 - kb * 64;
        if (avail >= 0) {
            const uint32_t stg = sb + AT_STG0 + (kb & 1) * AT_STGB;
            const int ntS  = min(8, (avail >> 3) + 1);
            const int ksPV = min(4, (avail >> 4) + 1);

            float s[8][4];
#pragma unroll
            for (int nt = 0; nt < 8; nt++)
#pragma unroll
                for (int r = 0; r < 4; r++) s[nt][r] = 0.f;

#pragma unroll
            for (int ks = 0; ks < 4; ks++) {
                uint32_t ah[4], al[4];
                int arow = wid * 16 + ra;
                int ach = (ks * 2 + ca) ^ (arow & 7);
                uint32_t ad = sb + AT_Q + arow * 128 + ach * 16;
                ldsm_x4(ah, ad);
                ldsm_x4(al, ad + 16384);
#pragma unroll
                for (int g = 0; g < 2; g++) {
                    const int nt0 = g * 4;
                    if (nt0 < ntS) {
                        uint32_t bhf[4][2], blf[4][2];
#pragma unroll
                        for (int np = 0; np < 2; np++) {
                            if (nt0 + np * 2 < ntS) {
                                int brow = (nt0 + np * 2 + jb_off) * 8 + rb;
                                int bch = (ks * 2 + kb_half) ^ (brow & 7);
                                uint32_t bd = stg + brow * 128 + bch * 16;
                                ldsm_x4(bhf[np * 2], bd);
                                ldsm_x4(blf[np * 2], bd + 8192);
                            }
                        }
#pragma unroll
                        for (int j = 0; j < 4; j++)
                            if (nt0 + j < ntS) mma_bf16(s[nt0 + j], ah, bhf[j]);
#pragma unroll
                        for (int j = 0; j < 4; j++)
                            if (nt0 + j < ntS) mma_bf16(s[nt0 + j], ah, blf[j]);
#pragma unroll
                        for (int j = 0; j < 4; j++)
                            if (nt0 + j < ntS) mma_bf16(s[nt0 + j], al, bhf[j]);
                    }
                }
            }

            if (kb * 64 + 63 > qw) {
#pragma unroll
                for (int nt = 0; nt < 8; nt++) {
#pragma unroll
                    for (int v = 0; v < 4; v++) {
                        int kg = kb * 64 + nt * 8 + c0 + (v & 1);
                        int qg = qw + r0 + ((v >> 1) << 3);
                        if (kg > qg) s[nt][v] = -1e30f;
                    }
                }
            }

#pragma unroll
            for (int hf = 0; hf < 2; hf++) {
                float mx = -1e30f;
#pragma unroll
                for (int nt = 0; nt < 8; nt++)
                    mx = fmaxf(mx, fmaxf(s[nt][hf * 2], s[nt][hf * 2 + 1]));
                mx = fmaxf(mx, __shfl_xor_sync(0xffffffffu, mx, 1));
                mx = fmaxf(mx, __shfl_xor_sync(0xffffffffu, mx, 2));
                const float mn = fmaxf(m[hf], mx);
                const float sc = __expf(m[hf] - mn);
                float rs = 0.f;
#pragma unroll
                for (int nt = 0; nt < 8; nt++) {
                    float e0 = __expf(s[nt][hf * 2] - mn);
                    float e1 = __expf(s[nt][hf * 2 + 1] - mn);
                    s[nt][hf * 2] = e0;
                    s[nt][hf * 2 + 1] = e1;
                    rs += e0 + e1;
                }
                rs += __shfl_xor_sync(0xffffffffu, rs, 1);
                rs += __shfl_xor_sync(0xffffffffu, rs, 2);
                l[hf] = l[hf] * sc + rs;
                m[hf] = mn;
#pragma unroll
                for (int nt = 0; nt < 8; nt++) {
                    o[nt][hf * 2] *= sc;
                    o[nt][hf * 2 + 1] *= sc;
                }
            }

            // ---- O += P @ V, V tile is [key][d]; B-fragments via ldsm trans ----
#pragma unroll
            for (int ks = 0; ks < 4; ks++) {
                if (ks < ksPV) {
                    uint32_t phi[4], plo[4];
#pragma unroll
                    for (int t2 = 0; t2 < 2; t2++) {
                        const float* sv = s[ks * 2 + t2];
                        float h0 = __bfloat162float(__float2bfloat16(sv[0]));
                        float h1 = __bfloat162float(__float2bfloat16(sv[1]));
                        float h2 = __bfloat162float(__float2bfloat16(sv[2]));
                        float h3 = __bfloat162float(__float2bfloat16(sv[3]));
                        phi[t2 * 2 + 0] = packbf(h0, h1);
                        phi[t2 * 2 + 1] = packbf(h2, h3);
                        plo[t2 * 2 + 0] = packbf(sv[0] - h0, sv[1] - h1);
                        plo[t2 * 2 + 1] = packbf(sv[2] - h2, sv[3] - h3);
                    }
#pragma unroll
                    for (int g = 0; g < 2; g++) {
                        const int nt0 = g * 4;
                        uint32_t vhf[4][2], vlf[4][2];
#pragma unroll
                        for (int np = 0; np < 2; np++) {
                            int krow = ks * 16 + kb_half * 8 + rb;        // key row
                            int dch = nt0 + np * 2 + jb_off;              // d chunk
                            int bch = dch ^ (krow & 7);
                            uint32_t bd = stg + 16384 + krow * 128 + bch * 16;
                            ldsm_x4t(vhf[np * 2], bd);
                            ldsm_x4t(vlf[np * 2], bd + 8192);
                        }
#pragma unroll
                        for (int j = 0; j < 4; j++)
                            mma_bf16(o[nt0 + j], phi, vhf[j]);
#pragma unroll
                        for (int j = 0; j < 4; j++)
                            mma_bf16(o[nt0 + j], phi, vlf[j]);
#pragma unroll
                        for (int j = 0; j < 4; j++)
                            mma_bf16(o[nt0 + j], plo, vhf[j]);
                    }
                }
            }
        }
        __syncthreads();
    }

    // epilogue: att = O / l * 0.125, written as fp16 hi/lo split
    const float inv0 = 0.125f / l[0];
    const float inv1 = 0.125f / l[1];
    const size_t row0 = (size_t)(b * SEQL + qw + r0);
#pragma unroll
    for (int nt = 0; nt < 8; nt++) {
        const int col = h * DHEAD + nt * 8 + c0;
        float a0 = o[nt][0] * inv0, a1 = o[nt][1] * inv0;
        float a2 = o[nt][2] * inv1, a3 = o[nt][3] * inv1;
        __half h0 = __float2half(a0), h1 = __float2half(a1);
        __half h2 = __float2half(a2), h3 = __float2half(a3);
        size_t o0 = row0 * DMODEL + col;
        size_t o1 = (row0 + 8) * DMODEL + col;
        *(__half2*)(Ohi + o0) = __halves2half2(h0, h1);
        *(__half2*)(Olo + o0) = __halves2half2(__float2half(a0 - __half2float(h0)),
                                               __float2half(a1 - __half2float(h1)));
        *(__half2*)(Ohi + o1) = __halves2half2(h2, h3);
        *(__half2*)(Olo + o1) = __halves2half2(__float2half(a2 - __half2float(h2)),
                                               __float2half(a3 - __half2float(h3)));
    }
}

// ---------------------------------------------------------------------------
// Launch
// ---------------------------------------------------------------------------
extern "C" void kernel_launch(void* const* d_in, const int* in_sizes, int n_in,
                              void* d_out, int out_size) {
    const float* q  = (const float*)d_in[0];
    const float* k  = (const float*)d_in[1];
    const float* v  = (const float*)d_in[2];
    const float* Wq = (const float*)d_in[4];
    const float* Wk = (const float*)d_in[5];
    const float* Wv = (const float*)d_in[6];
    const float* Wo = (const float*)d_in[7];
    float* out = (float*)d_out;

    void *pi3h, *pi3l, *pw4h, *pqh, *pql, *pkh, *pkl, *pvh2, *pvl2, *pah, *pal;
    cudaGetSymbolAddress(&pi3h, g_in3hi);
    cudaGetSymbolAddress(&pi3l, g_in3lo);
    cudaGetSymbolAddress(&pw4h, g_w4hi);
    cudaGetSymbolAddress(&pqh, g_qhi);
    cudaGetSymbolAddress(&pql, g_qlo);
    cudaGetSymbolAddress(&pkh, g_khi);
    cudaGetSymbolAddress(&pkl, g_klo);
    cudaGetSymbolAddress(&pvh2, g_vhi);
    cudaGetSymbolAddress(&pvl2, g_vlo);
    cudaGetSymbolAddress(&pah, g_atthi);
    cudaGetSymbolAddress(&pal, g_attlo);

    __half* i3h = (__half*)pi3h;
    __half* i3l = (__half*)pi3l;
    __half* w4h = (__half*)pw4h;
    const size_t WS = (size_t)DMODEL * DMODEL;

    cudaFuncSetAttribute(gemm_qkv, cudaFuncAttributeMaxDynamicSharedMemorySize, SMEM_GEMM);
    cudaFuncSetAttribute(gemm_wo,  cudaFuncAttributeMaxDynamicSharedMemorySize, SMEM_GEMM);
    cudaFuncSetAttribute(attn_tc, cudaFuncAttributeMaxDynamicSharedMemorySize, SMEM_ATT);

    const int n4 = (BLROWS * DMODEL) / 4;
    const dim3 tb(32, 8);

    split3<<<dim3((n4 / 4 + 255) / 256, 1, 3), 256>>>(q, k, v, i3h, i3l, n4);
    splitT4<<<dim3(32, 32, 4), tb>>>(Wq, Wk, Wv, Wo, w4h);

    gemm_qkv<<<dim3(DMODEL / 128, BLROWS / 128, 3), GEMM_THREADS, SMEM_GEMM>>>(
        i3h, i3l, w4h,
        (__nv_bfloat16*)pqh, (__nv_bfloat16*)pql,
        (__nv_bfloat16*)pkh, (__nv_bfloat16*)pkl,
        (__nv_bfloat16*)pvh2, (__nv_bfloat16*)pvl2);

    attn_tc<<<dim3(NHEAD * BATCH, SEQL / 128, 1), 256, SMEM_ATT>>>(
        (const __nv_bfloat16*)pqh, (const __nv_bfloat16*)pql,
        (const __nv_bfloat16*)pkh, (const __nv_bfloat16*)pkl,
        (const __nv_bfloat16*)pvh2, (const __nv_bfloat16*)pvl2,
        (__half*)pah, (__half*)pal);

    gemm_wo<<<dim3(DMODEL / 128, BLROWS / 128), GEMM_THREADS, SMEM_GEMM>>>(
        (const __half*)pah, (const __half*)pal, w4h + 3 * WS, out);
}

// round 15
// speedup vs baseline: 1.0797x; 1.0797x over previous
#include <cuda_runtime.h>
#include <cuda_bf16.h>
#include <cuda_fp16.h>
#include <cstdint>

// Problem constants
#define BATCH 2
#define SEQL  2048
#define DMODEL 1024
#define NHEAD 16
#define DHEAD 64
#define BLROWS (BATCH * SEQL)   // 4096
#define GK 1024

// ---------------------------------------------------------------------------
// Scratch
// ---------------------------------------------------------------------------
__device__ __half g_in3hi[(size_t)3 * BLROWS * DMODEL];                 // q,k,v split (fp16)
__device__ __half g_in3lo[(size_t)3 * BLROWS * DMODEL];
__device__ __half g_w4hi[(size_t)4 * DMODEL * DMODEL];                  // W^T rounded fp16
__device__ __nv_bfloat16 g_qhi[(size_t)BLROWS * DMODEL];
__device__ __nv_bfloat16 g_qlo[(size_t)BLROWS * DMODEL];
__device__ __nv_bfloat16 g_khi[(size_t)BLROWS * DMODEL];
__device__ __nv_bfloat16 g_klo[(size_t)BLROWS * DMODEL];
__device__ __half g_vf[(size_t)BLROWS * DMODEL];                        // V proj, fp16, token-major
__device__ __half g_atthi[(size_t)BLROWS * DMODEL];                     // attention out (fp16 split)
__device__ __half g_attlo[(size_t)BLROWS * DMODEL];

// ---------------------------------------------------------------------------
// PTX helpers
// ---------------------------------------------------------------------------
__device__ __forceinline__ uint32_t s2u(const void* p) {
    uint32_t a;
    asm("{ .reg .u64 t; cvta.to.shared.u64 t, %1; cvt.u32.u64 %0, t; }"
        : "=r"(a) : "l"(p));
    return a;
}
__device__ __forceinline__ void ldsm_x4(uint32_t* r, uint32_t addr) {
    asm volatile("ldmatrix.sync.aligned.m8n8.x4.shared.b16 {%0,%1,%2,%3}, [%4];"
                 : "=r"(r[0]), "=r"(r[1]), "=r"(r[2]), "=r"(r[3]) : "r"(addr));
}
__device__ __forceinline__ void ldsm_x4t(uint32_t* r, uint32_t addr) {
    asm volatile("ldmatrix.sync.aligned.m8n8.x4.trans.shared.b16 {%0,%1,%2,%3}, [%4];"
                 : "=r"(r[0]), "=r"(r[1]), "=r"(r[2]), "=r"(r[3]) : "r"(addr));
}
// bf16 mma (attention S)
__device__ __forceinline__ void mma_bf16(float* d, const uint32_t* a, const uint32_t* b) {
    asm volatile("mma.sync.aligned.m16n8k16.row.col.f32.bf16.bf16.f32 "
                 "{%0,%1,%2,%3}, {%4,%5,%6,%7}, {%8,%9}, {%0,%1,%2,%3};"
                 : "+f"(d[0]), "+f"(d[1]), "+f"(d[2]), "+f"(d[3])
                 : "r"(a[0]), "r"(a[1]), "r"(a[2]), "r"(a[3]), "r"(b[0]), "r"(b[1]));
}
// fp16 mma (projection GEMMs + attention PV)
__device__ __forceinline__ void mma_f16(float* d, const uint32_t* a, const uint32_t* b) {
    asm volatile("mma.sync.aligned.m16n8k16.row.col.f32.f16.f16.f32 "
                 "{%0,%1,%2,%3}, {%4,%5,%6,%7}, {%8,%9}, {%0,%1,%2,%3};"
                 : "+f"(d[0]), "+f"(d[1]), "+f"(d[2]), "+f"(d[3])
                 : "r"(a[0]), "r"(a[1]), "r"(a[2]), "r"(a[3]), "r"(b[0]), "r"(b[1]));
}
__device__ __forceinline__ void cpa16(uint32_t saddr, const void* g) {
    asm volatile("cp.async.cg.shared.global [%0], [%1], 16;" :: "r"(saddr), "l"(g));
}
#define CP_COMMIT() asm volatile("cp.async.commit_group;" ::: "memory")
#define CP_WAIT1()  asm volatile("cp.async.wait_group 1;" ::: "memory")
#define CP_WAIT0()  asm volatile("cp.async.wait_group 0;" ::: "memory")

__device__ __forceinline__ uint32_t packbf(float lo, float hi) {
    uint32_t d;
    asm("cvt.rn.bf16x2.f32 %0, %1, %2;" : "=r"(d) : "f"(hi), "f"(lo));
    return d;
}
__device__ __forceinline__ uint32_t packh(float lo, float hi) {
    uint32_t d;
    asm("cvt.rn.f16x2.f32 %0, %1, %2;" : "=r"(d) : "f"(hi), "f"(lo));
    return d;
}

// ---------------------------------------------------------------------------
// Conversion kernels
// ---------------------------------------------------------------------------
// q,k,v fp32 -> fp16 hi/lo (exact split). 4 coalesced float4 per thread.
__global__ __launch_bounds__(256) void split3(const float* __restrict__ q,
                                              const float* __restrict__ k,
                                              const float* __restrict__ v,
                                              __half* __restrict__ hi,
                                              __half* __restrict__ lo,
                                              int n4) {
    const int base = blockIdx.x * 1024 + threadIdx.x;
    const int z = blockIdx.z;
    const float* in = (z == 0) ? q : (z == 1) ? k : v;
    const size_t off = (size_t)z * BLROWS * DMODEL / 2;   // half2 units
    float4 val[4];
#pragma unroll
    for (int t = 0; t < 4; t++) {
        int i = base + t * 256;
        if (i < n4) val[t] = ((const float4*)in)[i];
    }
#pragma unroll
    for (int t = 0; t < 4; t++) {
        const int i = base + t * 256;
        if (i < n4) {
            __half h0 = __float2half(val[t].x);
            __half h1 = __float2half(val[t].y);
            __half h2 = __float2half(val[t].z);
            __half h3 = __float2half(val[t].w);
            __half l0 = __float2half(val[t].x - __half2float(h0));
            __half l1 = __float2half(val[t].y - __half2float(h1));
            __half l2 = __float2half(val[t].z - __half2float(h2));
            __half l3 = __float2half(val[t].w - __half2float(h3));
            ((__half2*)hi)[off + 2 * i]     = __halves2half2(h0, h1);
            ((__half2*)hi)[off + 2 * i + 1] = __halves2half2(h2, h3);
            ((__half2*)lo)[off + 2 * i]     = __halves2half2(l0, l1);
            ((__half2*)lo)[off + 2 * i + 1] = __halves2half2(l2, l3);
        }
    }
}

// W [K][N] fp32 -> Wt [N][K] fp16 (transposed, rounded), all four weights.
__global__ __launch_bounds__(256) void splitT4(const float* __restrict__ w0,
                                               const float* __restrict__ w1,
                                               const float* __restrict__ w2,
                                               const float* __restrict__ w3,
                                               __half* __restrict__ th) {
    __shared__ float t[32][33];
    const int tx = threadIdx.x, ty = threadIdx.y;
    const int n0 = blockIdx.x * 32, k0 = blockIdx.y * 32;
    const int z = blockIdx.z;
    const float* W = (z == 0) ? w0 : (z == 1) ? w1 : (z == 2) ? w2 : w3;
    const size_t zoff = (size_t)z * DMODEL * DMODEL;
#pragma unroll
    for (int i = 0; i < 32; i += 8)
        t[ty + i][tx] = W[(size_t)(k0 + ty + i) * DMODEL + n0 + tx];
    __syncthreads();
#pragma unroll
    for (int i = 0; i < 32; i += 8) {
        float x = t[tx][ty + i];
        th[zoff + (size_t)(n0 + ty + i) * DMODEL + k0 + tx] = __float2half(x);
    }
}

// ---------------------------------------------------------------------------
// fp16 2-pass GEMM: C = (A_hi + A_lo) @ B_hi   (= A @ fp16(W), error ~2^-12)
// 128x128 block, 4 warps (64x64 warp tiles), 3-stage pipeline, K-chunk 32.
// Epilogue mode: 0 = fp32, 1 = bf16 hi/lo split, 2 = fp16 rounded.
// ---------------------------------------------------------------------------
#define GBUF   8192u                 // one 128x32 fp16 tile
#define GSTG   24576u                // 3 tiles per stage
#define SMEM_GEMM (3u * GSTG)        // 73728
#define GEMM_THREADS 128

__device__ __forceinline__ void stage_load32(const __half* __restrict__ Ahi,
                                             const __half* __restrict__ Alo,
                                             const __half* __restrict__ B,
                                             int am0, int bn0, int k0,
                                             uint32_t sbase, int tid) {
#pragma unroll
    for (int b = 0; b < 3; b++) {
        const __half* g = (b == 0) ? Ahi : (b == 1) ? Alo : B;
        const int r0 = (b < 2) ? am0 : bn0;
        const uint32_t sbuf = sbase + b * GBUF;
#pragma unroll
        for (int t = 0; t < 4; t++) {
            int u = tid + t * GEMM_THREADS;
            int row = u >> 2, c = u & 3;
            int sw = c ^ ((row >> 1) & 3);
            cpa16(sbuf + row * 64 + sw * 16,
                  g + (size_t)(r0 + row) * GK + k0 + c * 8);
        }
    }
}

__device__ __forceinline__ void gemm_body(const __half* __restrict__ Ahi,
                                          const __half* __restrict__ Alo,
                                          const __half* __restrict__ B,
                                          float* __restrict__ C,
                                          __nv_bfloat16* __restrict__ Chi,
                                          __nv_bfloat16* __restrict__ Clo,
                                          __half* __restrict__ Ch,
                                          int N, int mode, uint32_t sb,
                                          int bm, int bn) {
    const int tid = threadIdx.x;
    const int wid = tid >> 5, lane = tid & 31;
    const int wm = wid & 1;          // 64-row slab
    const int wn = wid >> 1;         // 64-col slab
    const int am0 = bm * 128, bn0 = bn * 128;

    float acc[4][8][4];
#pragma unroll
    for (int i = 0; i < 4; i++)
#pragma unroll
        for (int j = 0; j < 8; j++)
#pragma unroll
            for (int r = 0; r < 4; r++) acc[i][j][r] = 0.f;

    const int NC = GK / 32;          // 32 chunks
    stage_load32(Ahi, Alo, B, am0, bn0, 0, sb, tid);
    CP_COMMIT();
    stage_load32(Ahi, Alo, B, am0, bn0, 32, sb + GSTG, tid);
    CP_COMMIT();

    const int ra = lane & 15, ca = lane >> 4;
    const int jb_off = (lane >> 4) & 1;
    const int kb_half = (lane >> 3) & 1;
    const int rb = lane & 7;
    int stg = 0;
    for (int c = 0; c < NC; c++) {
        if (c < NC - 1) CP_WAIT1(); else CP_WAIT0();
        __syncthreads();

        const uint32_t base = sb + stg * GSTG;
#pragma unroll
        for (int ks = 0; ks < 2; ks++) {
            uint32_t ah[4][4], al[4][4];
#pragma unroll
            for (int i = 0; i < 4; i++) {
                int row = wm * 64 + i * 16 + ra;
                int ch = (ks * 2 + ca) ^ ((row >> 1) & 3);
                uint32_t ad = base + row * 64 + ch * 16;
                ldsm_x4(ah[i], ad);
                ldsm_x4(al[i], ad + GBUF);
            }
            uint32_t bh[8][2];
#pragma unroll
            for (int jp = 0; jp < 4; jp++) {
                int row = wn * 64 + (jp * 2 + jb_off) * 8 + rb;
                int ch = (ks * 2 + kb_half) ^ ((row >> 1) & 3);
                uint32_t bd = base + 2 * GBUF + row * 64 + ch * 16;
                ldsm_x4(bh[jp * 2], bd);
            }
#pragma unroll
            for (int i = 0; i < 4; i++)
#pragma unroll
                for (int j = 0; j < 8; j++)
                    mma_f16(acc[i][j], ah[i], bh[j]);
#pragma unroll
            for (int i = 0; i < 4; i++)
#pragma unroll
                for (int j = 0; j < 8; j++)
                    mma_f16(acc[i][j], al[i], bh[j]);
        }

        if (c + 2 < NC) {
            stage_load32(Ahi, Alo, B, am0, bn0, (c + 2) * 32,
                         sb + ((stg + 2) % 3) * GSTG, tid);
            CP_COMMIT();
        }
        stg = (stg + 1) % 3;
    }

    const int r0 = lane >> 2, c0 = (lane & 3) * 2;
#pragma unroll
    for (int i = 0; i < 4; i++) {
#pragma unroll
        for (int j = 0; j < 8; j++) {
            const int grow = am0 + wm * 64 + i * 16 + r0;
            const int gcol = bn0 + wn * 64 + j * 8 + c0;
            if (mode == 0) {
                float2 v0 = {acc[i][j][0], acc[i][j][1]};
                float2 v1 = {acc[i][j][2], acc[i][j][3]};
                *(float2*)(C + (size_t)grow * N + gcol)       = v0;
                *(float2*)(C + (size_t)(grow + 8) * N + gcol) = v1;
            } else if (mode == 1) {
#pragma unroll
                for (int half = 0; half < 2; half++) {
                    float a0 = acc[i][j][half * 2], a1 = acc[i][j][half * 2 + 1];
                    float h0 = __bfloat162float(__float2bfloat16(a0));
                    float h1 = __bfloat162float(__float2bfloat16(a1));
                    size_t o = (size_t)(grow + half * 8) * N + gcol;
                    *(uint32_t*)(Chi + o) = packbf(h0, h1);
                    *(uint32_t*)(Clo + o) = packbf(a0 - h0, a1 - h1);
                }
            } else {
#pragma unroll
                for (int half = 0; half < 2; half++) {
                    size_t o = (size_t)(grow + half * 8) * N + gcol;
                    *(uint32_t*)(Ch + o) = packh(acc[i][j][half * 2],
                                                 acc[i][j][half * 2 + 1]);
                }
            }
        }
    }
}

// Fused Q/K/V projections: grid (8, 32, 3). Q/K -> bf16 hi/lo, V -> fp16.
__global__ __launch_bounds__(GEMM_THREADS, 2) void gemm_qkv(const __half* __restrict__ i3h,
                                                            const __half* __restrict__ i3l,
                                                            const __half* __restrict__ w4h,
                                                            __nv_bfloat16* __restrict__ qhi,
                                                            __nv_bfloat16* __restrict__ qlo,
                                                            __nv_bfloat16* __restrict__ khi,
                                                            __nv_bfloat16* __restrict__ klo,
                                                            __half* __restrict__ vf) {
    extern __shared__ char sm[];
    const uint32_t sb = s2u(sm);
    const int z = blockIdx.z;
    const size_t IS = (size_t)BLROWS * DMODEL;
    const size_t WS = (size_t)DMODEL * DMODEL;
    __nv_bfloat16* Chi = (z == 0) ? qhi : khi;
    __nv_bfloat16* Clo = (z == 0) ? qlo : klo;
    gemm_body(i3h + (size_t)z * IS, i3l + (size_t)z * IS, w4h + (size_t)z * WS,
              nullptr, Chi, Clo, vf, DMODEL, (z < 2) ? 1 : 2, sb,
              blockIdx.y, blockIdx.x);
}

// Wo projection, fp32 out
__global__ __launch_bounds__(GEMM_THREADS, 2) void gemm_wo(const __half* __restrict__ Ahi,
                                                           const __half* __restrict__ Alo,
                                                           const __half* __restrict__ B,
                                                           float* __restrict__ C) {
    extern __shared__ char sm[];
    const uint32_t sb = s2u(sm);
    gemm_body(Ahi, Alo, B, C, nullptr, nullptr, nullptr, DMODEL, 0, sb,
              blockIdx.y, blockIdx.x);
}

// ---------------------------------------------------------------------------
// Tensor-core causal flash attention.
// S: bf16 3-pass (Qhi/Qlo x Khi/Klo). PV: fp16 2-pass (P exact split x fp16 V).
// K token-major bf16 hi/lo; V token-major fp16, B-fragments via ldmatrix.trans.
// Stage = Khi(8K) + Klo(8K) + V(8K) = 24KB; smem total 80KB (2 CTAs/SM).
// ---------------------------------------------------------------------------
#define AT_Q    0u
#define AT_STG0 32768u
#define AT_STGB 24576u
#define AT_VOFF 16384u
#define SMEM_ATT (AT_STG0 + 2u * AT_STGB)   // 81920

__device__ __forceinline__ void att_load_kv(const __nv_bfloat16* __restrict__ Khi,
                                            const __nv_bfloat16* __restrict__ Klo,
                                            const __half* __restrict__ Vf,
                                            int b, int h, int kb,
                                            uint32_t stg, int tid) {
    const size_t gb = (size_t)(b * SEQL + kb * 64) * DMODEL + h * DHEAD;
#pragma unroll
    for (int t = 0; t < 2; t++) {
        int u = tid + t * 256;
        int row = u >> 3, c = u & 7;
        uint32_t soff = row * 128 + ((c ^ (row & 7)) * 16);
        const size_t goff = gb + (size_t)row * DMODEL + c * 8;
        cpa16(stg + soff,            Khi + goff);
        cpa16(stg + 8192 + soff,     Klo + goff);
        cpa16(stg + AT_VOFF + soff,  Vf + goff);
    }
}

__global__ __launch_bounds__(256, 2) void attn_tc(const __nv_bfloat16* __restrict__ Qhi,
                                                  const __nv_bfloat16* __restrict__ Qlo,
                                                  const __nv_bfloat16* __restrict__ Khi,
                                                  const __nv_bfloat16* __restrict__ Klo,
                                                  const __half* __restrict__ Vf,
                                                  __half* __restrict__ Ohi,
                                                  __half* __restrict__ Olo) {
    extern __shared__ char sm[];
    const uint32_t sb = s2u(sm);
    const int tid = threadIdx.x;
    const int wid = tid >> 5, lane = tid & 31;
    const int qb = (int)gridDim.y - 1 - (int)blockIdx.y;   // heavy tiles first
    const int h = blockIdx.x & 15, b = blockIdx.x >> 4;

    {
        const size_t qgb = (size_t)(b * SEQL + qb * 128) * DMODEL + h * DHEAD;
#pragma unroll
        for (int t = 0; t < 4; t++) {
            int u = tid + t * 256;
            int row = u >> 3, c = u & 7;
            uint32_t soff = row * 128 + ((c ^ (row & 7)) * 16);
            cpa16(sb + AT_Q + soff,         Qhi + qgb + (size_t)row * DMODEL + c * 8);
            cpa16(sb + AT_Q + 16384 + soff, Qlo + qgb + (size_t)row * DMODEL + c * 8);
        }
    }
    CP_COMMIT();

    float o[8][4];
#pragma unroll
    for (int nt = 0; nt < 8; nt++)
#pragma unroll
        for (int r = 0; r < 4; r++) o[nt][r] = 0.f;
    float m[2] = {-1e30f, -1e30f};
    float l[2] = {0.f, 0.f};

    const int qw = qb * 128 + wid * 16;
    const int r0 = lane >> 2, c0 = (lane & 3) * 2;
    const int ra = lane & 15, ca = lane >> 4;
    const int jb_off = (lane >> 4) & 1;      // which tile of the ldsm_x4 pair
    const int kb_half = (lane >> 3) & 1;     // k-half within the pair
    const int rb = lane & 7;
    const int last = 2 * qb + 1;

    att_load_kv(Khi, Klo, Vf, b, h, 0, sb + AT_STG0, tid);
    CP_COMMIT();

    for (int kb = 0; kb <= last; kb++) {
        if (kb < last) {
            att_load_kv(Khi, Klo, Vf, b, h, kb + 1,
                        sb + AT_STG0 + ((kb + 1) & 1) * AT_STGB, tid);
            CP_COMMIT();
            CP_WAIT1();
        } else {
            CP_WAIT0();
        }
        __syncthreads();

        const int avail = qw + 15 - kb * 64;
        if (avail >= 0) {
            const uint32_t stg = sb + AT_STG0 + (kb & 1) * AT_STGB;
            const int ntS  = min(8, (avail >> 3) + 1);
            const int ksPV = min(4, (avail >> 4) + 1);

            float s[8][4];
#pragma unroll
            for (int nt = 0; nt < 8; nt++)
#pragma unroll
                for (int r = 0; r < 4; r++) s[nt][r] = 0.f;

#pragma unroll
            for (int ks = 0; ks < 4; ks++) {
                uint32_t ah[4], al[4];
                int arow = wid * 16 + ra;
                int ach = (ks * 2 + ca) ^ (arow & 7);
                uint32_t ad = sb + AT_Q + arow * 128 + ach * 16;
                ldsm_x4(ah, ad);
                ldsm_x4(al, ad + 16384);
#pragma unroll
                for (int g = 0; g < 2; g++) {
                    const int nt0 = g * 4;
                    if (nt0 < ntS) {
                        uint32_t bhf[4][2], blf[4][2];
#pragma unroll
                        for (int np = 0; np < 2; np++) {
                            if (nt0 + np * 2 < ntS) {
                                int brow = (nt0 + np * 2 + jb_off) * 8 + rb;
                                int bch = (ks * 2 + kb_half) ^ (brow & 7);
                                uint32_t bd = stg + brow * 128 + bch * 16;
                                ldsm_x4(bhf[np * 2], bd);
                                ldsm_x4(blf[np * 2], bd + 8192);
                            }
                        }
#pragma unroll
                        for (int j = 0; j < 4; j++)
                            if (nt0 + j < ntS) mma_bf16(s[nt0 + j], ah, bhf[j]);
#pragma unroll
                        for (int j = 0; j < 4; j++)
                            if (nt0 + j < ntS) mma_bf16(s[nt0 + j], ah, blf[j]);
#pragma unroll
                        for (int j = 0; j < 4; j++)
                            if (nt0 + j < ntS) mma_bf16(s[nt0 + j], al, bhf[j]);
                    }
                }
            }

            if (kb * 64 + 63 > qw) {
#pragma unroll
                for (int nt = 0; nt < 8; nt++) {
#pragma unroll
                    for (int v = 0; v < 4; v++) {
                        int kg = kb * 64 + nt * 8 + c0 + (v & 1);
                        int qg = qw + r0 + ((v >> 1) << 3);
                        if (kg > qg) s[nt][v] = -1e30f;
                    }
                }
            }

#pragma unroll
            for (int hf = 0; hf < 2; hf++) {
                float mx = -1e30f;
#pragma unroll
                for (int nt = 0; nt < 8; nt++)
                    mx = fmaxf(mx, fmaxf(s[nt][hf * 2], s[nt][hf * 2 + 1]));
                mx = fmaxf(mx, __shfl_xor_sync(0xffffffffu, mx, 1));
                mx = fmaxf(mx, __shfl_xor_sync(0xffffffffu, mx, 2));
                const float mn = fmaxf(m[hf], mx);
                const float sc = __expf(m[hf] - mn);
                float rs = 0.f;
#pragma unroll
                for (int nt = 0; nt < 8; nt++) {
                    float e0 = __expf(s[nt][hf * 2] - mn);
                    float e1 = __expf(s[nt][hf * 2 + 1] - mn);
                    s[nt][hf * 2] = e0;
                    s[nt][hf * 2 + 1] = e1;
                    rs += e0 + e1;
                }
                rs += __shfl_xor_sync(0xffffffffu, rs, 1);
                rs += __shfl_xor_sync(0xffffffffu, rs, 2);
                l[hf] = l[hf] * sc + rs;
                m[hf] = mn;
#pragma unroll
                for (int nt = 0; nt < 8; nt++) {
                    o[nt][hf * 2] *= sc;
                    o[nt][hf * 2 + 1] *= sc;
                }
            }

            // ---- O += P @ V: P exact fp16 split, V fp16, 2 passes ----
#pragma unroll
            for (int ks = 0; ks < 4; ks++) {
                if (ks < ksPV) {
                    uint32_t phi[4], plo[4];
#pragma unroll
                    for (int t2 = 0; t2 < 2; t2++) {
                        const float* sv = s[ks * 2 + t2];
                        float h0 = __half2float(__float2half(sv[0]));
                        float h1 = __half2float(__float2half(sv[1]));
                        float h2 = __half2float(__float2half(sv[2]));
                        float h3 = __half2float(__float2half(sv[3]));
                        phi[t2 * 2 + 0] = packh(h0, h1);
                        phi[t2 * 2 + 1] = packh(h2, h3);
                        plo[t2 * 2 + 0] = packh(sv[0] - h0, sv[1] - h1);
                        plo[t2 * 2 + 1] = packh(sv[2] - h2, sv[3] - h3);
                    }
#pragma unroll
                    for (int g = 0; g < 2; g++) {
                        const int nt0 = g * 4;
                        uint32_t vhf[4][2];
#pragma unroll
                        for (int np = 0; np < 2; np++) {
                            int krow = ks * 16 + kb_half * 8 + rb;        // key row
                            int dch = nt0 + np * 2 + jb_off;              // d chunk
                            int bch = dch ^ (krow & 7);
                            uint32_t bd = stg + AT_VOFF + krow * 128 + bch * 16;
                            ldsm_x4t(vhf[np * 2], bd);
                        }
#pragma unroll
                        for (int j = 0; j < 4; j++)
                            mma_f16(o[nt0 + j], phi, vhf[j]);
#pragma unroll
                        for (int j = 0; j < 4; j++)
                            mma_f16(o[nt0 + j], plo, vhf[j]);
                    }
                }
            }
        }
        __syncthreads();
    }

    // epilogue: att = O / l * 0.125, written as fp16 hi/lo split
    const float inv0 = 0.125f / l[0];
    const float inv1 = 0.125f / l[1];
    const size_t row0 = (size_t)(b * SEQL + qw + r0);
#pragma unroll
    for (int nt = 0; nt < 8; nt++) {
        const int col = h * DHEAD + nt * 8 + c0;
        float a0 = o[nt][0] * inv0, a1 = o[nt][1] * inv0;
        float a2 = o[nt][2] * inv1, a3 = o[nt][3] * inv1;
        __half h0 = __float2half(a0), h1 = __float2half(a1);
        __half h2 = __float2half(a2), h3 = __float2half(a3);
        size_t o0 = row0 * DMODEL + col;
        size_t o1 = (row0 + 8) * DMODEL + col;
        *(__half2*)(Ohi + o0) = __halves2half2(h0, h1);
        *(__half2*)(Olo + o0) = __halves2half2(__float2half(a0 - __half2float(h0)),
                                               __float2half(a1 - __half2float(h1)));
        *(__half2*)(Ohi + o1) = __halves2half2(h2, h3);
        *(__half2*)(Olo + o1) = __halves2half2(__float2half(a2 - __half2float(h2)),
                                               __float2half(a3 - __half2float(h3)));
    }
}

// ---------------------------------------------------------------------------
// Launch
// ---------------------------------------------------------------------------
extern "C" void kernel_launch(void* const* d_in, const int* in_sizes, int n_in,
                              void* d_out, int out_size) {
    const float* q  = (const float*)d_in[0];
    const float* k  = (const float*)d_in[1];
    const float* v  = (const float*)d_in[2];
    const float* Wq = (const float*)d_in[4];
    const float* Wk = (const float*)d_in[5];
    const float* Wv = (const float*)d_in[6];
    const float* Wo = (const float*)d_in[7];
    float* out = (float*)d_out;

    void *pi3h, *pi3l, *pw4h, *pqh, *pql, *pkh, *pkl, *pvf, *pah, *pal;
    cudaGetSymbolAddress(&pi3h, g_in3hi);
    cudaGetSymbolAddress(&pi3l, g_in3lo);
    cudaGetSymbolAddress(&pw4h, g_w4hi);
    cudaGetSymbolAddress(&pqh, g_qhi);
    cudaGetSymbolAddress(&pql, g_qlo);
    cudaGetSymbolAddress(&pkh, g_khi);
    cudaGetSymbolAddress(&pkl, g_klo);
    cudaGetSymbolAddress(&pvf, g_vf);
    cudaGetSymbolAddress(&pah, g_atthi);
    cudaGetSymbolAddress(&pal, g_attlo);

    __half* i3h = (__half*)pi3h;
    __half* i3l = (__half*)pi3l;
    __half* w4h = (__half*)pw4h;
    const size_t WS = (size_t)DMODEL * DMODEL;

    cudaFuncSetAttribute(gemm_qkv, cudaFuncAttributeMaxDynamicSharedMemorySize, SMEM_GEMM);
    cudaFuncSetAttribute(gemm_wo,  cudaFuncAttributeMaxDynamicSharedMemorySize, SMEM_GEMM);
    cudaFuncSetAttribute(attn_tc, cudaFuncAttributeMaxDynamicSharedMemorySize, SMEM_ATT);

    const int n4 = (BLROWS * DMODEL) / 4;
    const dim3 tb(32, 8);

    split3<<<dim3((n4 / 4 + 255) / 256, 1, 3), 256>>>(q, k, v, i3h, i3l, n4);
    splitT4<<<dim3(32, 32, 4), tb>>>(Wq, Wk, Wv, Wo, w4h);

    gemm_qkv<<<dim3(DMODEL / 128, BLROWS / 128, 3), GEMM_THREADS, SMEM_GEMM>>>(
        i3h, i3l, w4h,
        (__nv_bfloat16*)pqh, (__nv_bfloat16*)pql,
        (__nv_bfloat16*)pkh, (__nv_bfloat16*)pkl, (__half*)pvf);

    attn_tc<<<dim3(NHEAD * BATCH, SEQL / 128, 1), 256, SMEM_ATT>>>(
        (const __nv_bfloat16*)pqh, (const __nv_bfloat16*)pql,
        (const __nv_bfloat16*)pkh, (const __nv_bfloat16*)pkl,
        (const __half*)pvf, (__half*)pah, (__half*)pal);

    gemm_wo<<<dim3(DMODEL / 128, BLROWS / 128), GEMM_THREADS, SMEM_GEMM>>>(
        (const __half*)pah, (const __half*)pal, w4h + 3 * WS, out);
}

// round 16
// speedup vs baseline: 1.1364x; 1.0525x over previous
#include <cuda_runtime.h>
#include <cuda_bf16.h>
#include <cuda_fp16.h>
#include <cstdint>

// Problem constants
#define BATCH 2
#define SEQL  2048
#define DMODEL 1024
#define NHEAD 16
#define DHEAD 64
#define BLROWS (BATCH * SEQL)   // 4096
#define GK 1024

// ---------------------------------------------------------------------------
// Scratch
// ---------------------------------------------------------------------------
__device__ __half g_in3hi[(size_t)3 * BLROWS * DMODEL];                 // q,k,v split (fp16)
__device__ __half g_in3lo[(size_t)3 * BLROWS * DMODEL];
__device__ __half g_w4hi[(size_t)4 * DMODEL * DMODEL];                  // W^T rounded fp16
__device__ __nv_bfloat16 g_qhi[(size_t)BLROWS * DMODEL];
__device__ __nv_bfloat16 g_qlo[(size_t)BLROWS * DMODEL];
__device__ __nv_bfloat16 g_khi[(size_t)BLROWS * DMODEL];
__device__ __nv_bfloat16 g_klo[(size_t)BLROWS * DMODEL];
__device__ __half g_vf[(size_t)BLROWS * DMODEL];                        // V proj, fp16, token-major
__device__ __half g_att[(size_t)BLROWS * DMODEL];                       // attention out (fp16)

// ---------------------------------------------------------------------------
// PTX helpers
// ---------------------------------------------------------------------------
__device__ __forceinline__ uint32_t s2u(const void* p) {
    uint32_t a;
    asm("{ .reg .u64 t; cvta.to.shared.u64 t, %1; cvt.u32.u64 %0, t; }"
        : "=r"(a) : "l"(p));
    return a;
}
__device__ __forceinline__ void ldsm_x4(uint32_t* r, uint32_t addr) {
    asm volatile("ldmatrix.sync.aligned.m8n8.x4.shared.b16 {%0,%1,%2,%3}, [%4];"
                 : "=r"(r[0]), "=r"(r[1]), "=r"(r[2]), "=r"(r[3]) : "r"(addr));
}
__device__ __forceinline__ void ldsm_x4t(uint32_t* r, uint32_t addr) {
    asm volatile("ldmatrix.sync.aligned.m8n8.x4.trans.shared.b16 {%0,%1,%2,%3}, [%4];"
                 : "=r"(r[0]), "=r"(r[1]), "=r"(r[2]), "=r"(r[3]) : "r"(addr));
}
// bf16 mma (attention S)
__device__ __forceinline__ void mma_bf16(float* d, const uint32_t* a, const uint32_t* b) {
    asm volatile("mma.sync.aligned.m16n8k16.row.col.f32.bf16.bf16.f32 "
                 "{%0,%1,%2,%3}, {%4,%5,%6,%7}, {%8,%9}, {%0,%1,%2,%3};"
                 : "+f"(d[0]), "+f"(d[1]), "+f"(d[2]), "+f"(d[3])
                 : "r"(a[0]), "r"(a[1]), "r"(a[2]), "r"(a[3]), "r"(b[0]), "r"(b[1]));
}
// fp16 mma (projection GEMMs + attention PV)
__device__ __forceinline__ void mma_f16(float* d, const uint32_t* a, const uint32_t* b) {
    asm volatile("mma.sync.aligned.m16n8k16.row.col.f32.f16.f16.f32 "
                 "{%0,%1,%2,%3}, {%4,%5,%6,%7}, {%8,%9}, {%0,%1,%2,%3};"
                 : "+f"(d[0]), "+f"(d[1]), "+f"(d[2]), "+f"(d[3])
                 : "r"(a[0]), "r"(a[1]), "r"(a[2]), "r"(a[3]), "r"(b[0]), "r"(b[1]));
}
__device__ __forceinline__ void cpa16(uint32_t saddr, const void* g) {
    asm volatile("cp.async.cg.shared.global [%0], [%1], 16;" :: "r"(saddr), "l"(g));
}
#define CP_COMMIT() asm volatile("cp.async.commit_group;" ::: "memory")
#define CP_WAIT1()  asm volatile("cp.async.wait_group 1;" ::: "memory")
#define CP_WAIT0()  asm volatile("cp.async.wait_group 0;" ::: "memory")

__device__ __forceinline__ uint32_t packbf(float lo, float hi) {
    uint32_t d;
    asm("cvt.rn.bf16x2.f32 %0, %1, %2;" : "=r"(d) : "f"(hi), "f"(lo));
    return d;
}
__device__ __forceinline__ uint32_t packh(float lo, float hi) {
    uint32_t d;
    asm("cvt.rn.f16x2.f32 %0, %1, %2;" : "=r"(d) : "f"(hi), "f"(lo));
    return d;
}

// ---------------------------------------------------------------------------
// Conversion kernels
// ---------------------------------------------------------------------------
// q,k,v fp32 -> fp16 hi/lo (exact split). 4 coalesced float4 per thread.
__global__ __launch_bounds__(256) void split3(const float* __restrict__ q,
                                              const float* __restrict__ k,
                                              const float* __restrict__ v,
                                              __half* __restrict__ hi,
                                              __half* __restrict__ lo,
                                              int n4) {
    const int base = blockIdx.x * 1024 + threadIdx.x;
    const int z = blockIdx.z;
    const float* in = (z == 0) ? q : (z == 1) ? k : v;
    const size_t off = (size_t)z * BLROWS * DMODEL / 2;   // half2 units
    float4 val[4];
#pragma unroll
    for (int t = 0; t < 4; t++) {
        int i = base + t * 256;
        if (i < n4) val[t] = ((const float4*)in)[i];
    }
#pragma unroll
    for (int t = 0; t < 4; t++) {
        const int i = base + t * 256;
        if (i < n4) {
            __half h0 = __float2half(val[t].x);
            __half h1 = __float2half(val[t].y);
            __half h2 = __float2half(val[t].z);
            __half h3 = __float2half(val[t].w);
            __half l0 = __float2half(val[t].x - __half2float(h0));
            __half l1 = __float2half(val[t].y - __half2float(h1));
            __half l2 = __float2half(val[t].z - __half2float(h2));
            __half l3 = __float2half(val[t].w - __half2float(h3));
            ((__half2*)hi)[off + 2 * i]     = __halves2half2(h0, h1);
            ((__half2*)hi)[off + 2 * i + 1] = __halves2half2(h2, h3);
            ((__half2*)lo)[off + 2 * i]     = __halves2half2(l0, l1);
            ((__half2*)lo)[off + 2 * i + 1] = __halves2half2(l2, l3);
        }
    }
}

// W [K][N] fp32 -> Wt [N][K] fp16 (transposed, rounded), all four weights.
__global__ __launch_bounds__(256) void splitT4(const float* __restrict__ w0,
                                               const float* __restrict__ w1,
                                               const float* __restrict__ w2,
                                               const float* __restrict__ w3,
                                               __half* __restrict__ th) {
    __shared__ float t[32][33];
    const int tx = threadIdx.x, ty = threadIdx.y;
    const int n0 = blockIdx.x * 32, k0 = blockIdx.y * 32;
    const int z = blockIdx.z;
    const float* W = (z == 0) ? w0 : (z == 1) ? w1 : (z == 2) ? w2 : w3;
    const size_t zoff = (size_t)z * DMODEL * DMODEL;
#pragma unroll
    for (int i = 0; i < 32; i += 8)
        t[ty + i][tx] = W[(size_t)(k0 + ty + i) * DMODEL + n0 + tx];
    __syncthreads();
#pragma unroll
    for (int i = 0; i < 32; i += 8) {
        float x = t[tx][ty + i];
        th[zoff + (size_t)(n0 + ty + i) * DMODEL + k0 + tx] = __float2half(x);
    }
}

// ---------------------------------------------------------------------------
// fp16 GEMM: C = (A_hi [+ A_lo]) @ B  (TWO=true: 2-pass exact-A; false: 1-pass)
// 128x128 block, 4 warps (64x64 warp tiles), 3-stage pipeline, K-chunk 32.
// Epilogue mode: 0 = fp32, 1 = bf16 hi/lo split, 2 = fp16 rounded.
// ---------------------------------------------------------------------------
#define GBUF   8192u                 // one 128x32 fp16 tile
#define GSTG   24576u                // 3 tiles per stage (2-pass layout)
#define SMEM_GEMM (3u * GSTG)        // 73728
#define GEMM_THREADS 128

template <bool TWO>
__device__ __forceinline__ void stage_load32(const __half* __restrict__ Ahi,
                                             const __half* __restrict__ Alo,
                                             const __half* __restrict__ B,
                                             int am0, int bn0, int k0,
                                             uint32_t sbase, int tid) {
#pragma unroll
    for (int b = 0; b < 3; b++) {
        if (!TWO && b == 1) continue;
        const __half* g = (b == 0) ? Ahi : (b == 1) ? Alo : B;
        const int r0 = (b < 2) ? am0 : bn0;
        const uint32_t sbuf = sbase + b * GBUF;
#pragma unroll
        for (int t = 0; t < 4; t++) {
            int u = tid + t * GEMM_THREADS;
            int row = u >> 2, c = u & 3;
            int sw = c ^ ((row >> 1) & 3);
            cpa16(sbuf + row * 64 + sw * 16,
                  g + (size_t)(r0 + row) * GK + k0 + c * 8);
        }
    }
}

template <bool TWO>
__device__ __forceinline__ void gemm_body(const __half* __restrict__ Ahi,
                                          const __half* __restrict__ Alo,
                                          const __half* __restrict__ B,
                                          float* __restrict__ C,
                                          __nv_bfloat16* __restrict__ Chi,
                                          __nv_bfloat16* __restrict__ Clo,
                                          __half* __restrict__ Ch,
                                          int N, int mode, uint32_t sb,
                                          int bm, int bn) {
    const int tid = threadIdx.x;
    const int wid = tid >> 5, lane = tid & 31;
    const int wm = wid & 1;          // 64-row slab
    const int wn = wid >> 1;         // 64-col slab
    const int am0 = bm * 128, bn0 = bn * 128;

    float acc[4][8][4];
#pragma unroll
    for (int i = 0; i < 4; i++)
#pragma unroll
        for (int j = 0; j < 8; j++)
#pragma unroll
            for (int r = 0; r < 4; r++) acc[i][j][r] = 0.f;

    const int NC = GK / 32;          // 32 chunks
    stage_load32<TWO>(Ahi, Alo, B, am0, bn0, 0, sb, tid);
    CP_COMMIT();
    stage_load32<TWO>(Ahi, Alo, B, am0, bn0, 32, sb + GSTG, tid);
    CP_COMMIT();

    const int ra = lane & 15, ca = lane >> 4;
    const int jb_off = (lane >> 4) & 1;
    const int kb_half = (lane >> 3) & 1;
    const int rb = lane & 7;
    int stg = 0;
    for (int c = 0; c < NC; c++) {
        if (c < NC - 1) CP_WAIT1(); else CP_WAIT0();
        __syncthreads();

        const uint32_t base = sb + stg * GSTG;
#pragma unroll
        for (int ks = 0; ks < 2; ks++) {
            uint32_t ah[4][4], al[4][4];
#pragma unroll
            for (int i = 0; i < 4; i++) {
                int row = wm * 64 + i * 16 + ra;
                int ch = (ks * 2 + ca) ^ ((row >> 1) & 3);
                uint32_t ad = base + row * 64 + ch * 16;
                ldsm_x4(ah[i], ad);
                if (TWO) ldsm_x4(al[i], ad + GBUF);
            }
            uint32_t bh[8][2];
#pragma unroll
            for (int jp = 0; jp < 4; jp++) {
                int row = wn * 64 + (jp * 2 + jb_off) * 8 + rb;
                int ch = (ks * 2 + kb_half) ^ ((row >> 1) & 3);
                uint32_t bd = base + 2 * GBUF + row * 64 + ch * 16;
                ldsm_x4(bh[jp * 2], bd);
            }
#pragma unroll
            for (int i = 0; i < 4; i++)
#pragma unroll
                for (int j = 0; j < 8; j++)
                    mma_f16(acc[i][j], ah[i], bh[j]);
            if (TWO) {
#pragma unroll
                for (int i = 0; i < 4; i++)
#pragma unroll
                    for (int j = 0; j < 8; j++)
                        mma_f16(acc[i][j], al[i], bh[j]);
            }
        }

        if (c + 2 < NC) {
            stage_load32<TWO>(Ahi, Alo, B, am0, bn0, (c + 2) * 32,
                              sb + ((stg + 2) % 3) * GSTG, tid);
            CP_COMMIT();
        }
        stg = (stg + 1) % 3;
    }

    const int r0 = lane >> 2, c0 = (lane & 3) * 2;
#pragma unroll
    for (int i = 0; i < 4; i++) {
#pragma unroll
        for (int j = 0; j < 8; j++) {
            const int grow = am0 + wm * 64 + i * 16 + r0;
            const int gcol = bn0 + wn * 64 + j * 8 + c0;
            if (mode == 0) {
                float2 v0 = {acc[i][j][0], acc[i][j][1]};
                float2 v1 = {acc[i][j][2], acc[i][j][3]};
                *(float2*)(C + (size_t)grow * N + gcol)       = v0;
                *(float2*)(C + (size_t)(grow + 8) * N + gcol) = v1;
            } else if (mode == 1) {
#pragma unroll
                for (int half = 0; half < 2; half++) {
                    float a0 = acc[i][j][half * 2], a1 = acc[i][j][half * 2 + 1];
                    float h0 = __bfloat162float(__float2bfloat16(a0));
                    float h1 = __bfloat162float(__float2bfloat16(a1));
                    size_t o = (size_t)(grow + half * 8) * N + gcol;
                    *(uint32_t*)(Chi + o) = packbf(h0, h1);
                    *(uint32_t*)(Clo + o) = packbf(a0 - h0, a1 - h1);
                }
            } else {
#pragma unroll
                for (int half = 0; half < 2; half++) {
                    size_t o = (size_t)(grow + half * 8) * N + gcol;
                    *(uint32_t*)(Ch + o) = packh(acc[i][j][half * 2],
                                                 acc[i][j][half * 2 + 1]);
                }
            }
        }
    }
}

// Fused Q/K/V projections: grid (8, 32, 3). Q/K -> bf16 hi/lo, V -> fp16.
__global__ __launch_bounds__(GEMM_THREADS, 2) void gemm_qkv(const __half* __restrict__ i3h,
                                                            const __half* __restrict__ i3l,
                                                            const __half* __restrict__ w4h,
                                                            __nv_bfloat16* __restrict__ qhi,
                                                            __nv_bfloat16* __restrict__ qlo,
                                                            __nv_bfloat16* __restrict__ khi,
                                                            __nv_bfloat16* __restrict__ klo,
                                                            __half* __restrict__ vf) {
    extern __shared__ char sm[];
    const uint32_t sb = s2u(sm);
    const int z = blockIdx.z;
    const size_t IS = (size_t)BLROWS * DMODEL;
    const size_t WS = (size_t)DMODEL * DMODEL;
    __nv_bfloat16* Chi = (z == 0) ? qhi : khi;
    __nv_bfloat16* Clo = (z == 0) ? qlo : klo;
    gemm_body<true>(i3h + (size_t)z * IS, i3l + (size_t)z * IS, w4h + (size_t)z * WS,
                    nullptr, Chi, Clo, vf, DMODEL, (z < 2) ? 1 : 2, sb,
                    blockIdx.y, blockIdx.x);
}

// Wo projection: single-pass (A = rounded fp16 att), fp32 out.
__global__ __launch_bounds__(GEMM_THREADS, 2) void gemm_wo(const __half* __restrict__ A,
                                                           const __half* __restrict__ B,
                                                           float* __restrict__ C) {
    extern __shared__ char sm[];
    const uint32_t sb = s2u(sm);
    gemm_body<false>(A, nullptr, B, C, nullptr, nullptr, nullptr, DMODEL, 0, sb,
                     blockIdx.y, blockIdx.x);
}

// ---------------------------------------------------------------------------
// Tensor-core causal flash attention.
// S: bf16 3-pass (Qhi/Qlo x Khi/Klo). PV: fp16 2-pass (P exact split x fp16 V).
// K token-major bf16 hi/lo; V token-major fp16, B-fragments via ldmatrix.trans.
// Stage = Khi(8K) + Klo(8K) + V(8K) = 24KB; smem total 80KB (2 CTAs/SM).
// Epilogue: att rounded to a single fp16 (Wo GEMM is 1-pass).
// ---------------------------------------------------------------------------
#define AT_Q    0u
#define AT_STG0 32768u
#define AT_STGB 24576u
#define AT_VOFF 16384u
#define SMEM_ATT (AT_STG0 + 2u * AT_STGB)   // 81920

__device__ __forceinline__ void att_load_kv(const __nv_bfloat16* __restrict__ Khi,
                                            const __nv_bfloat16* __restrict__ Klo,
                                            const __half* __restrict__ Vf,
                                            int b, int h, int kb,
                                            uint32_t stg, int tid) {
    const size_t gb = (size_t)(b * SEQL + kb * 64) * DMODEL + h * DHEAD;
#pragma unroll
    for (int t = 0; t < 2; t++) {
        int u = tid + t * 256;
        int row = u >> 3, c = u & 7;
        uint32_t soff = row * 128 + ((c ^ (row & 7)) * 16);
        const size_t goff = gb + (size_t)row * DMODEL + c * 8;
        cpa16(stg + soff,            Khi + goff);
        cpa16(stg + 8192 + soff,     Klo + goff);
        cpa16(stg + AT_VOFF + soff,  Vf + goff);
    }
}

__global__ __launch_bounds__(256, 2) void attn_tc(const __nv_bfloat16* __restrict__ Qhi,
                                                  const __nv_bfloat16* __restrict__ Qlo,
                                                  const __nv_bfloat16* __restrict__ Khi,
                                                  const __nv_bfloat16* __restrict__ Klo,
                                                  const __half* __restrict__ Vf,
                                                  __half* __restrict__ Oatt) {
    extern __shared__ char sm[];
    const uint32_t sb = s2u(sm);
    const int tid = threadIdx.x;
    const int wid = tid >> 5, lane = tid & 31;
    const int qb = (int)gridDim.y - 1 - (int)blockIdx.y;   // heavy tiles first
    const int h = blockIdx.x & 15, b = blockIdx.x >> 4;

    {
        const size_t qgb = (size_t)(b * SEQL + qb * 128) * DMODEL + h * DHEAD;
#pragma unroll
        for (int t = 0; t < 4; t++) {
            int u = tid + t * 256;
            int row = u >> 3, c = u & 7;
            uint32_t soff = row * 128 + ((c ^ (row & 7)) * 16);
            cpa16(sb + AT_Q + soff,         Qhi + qgb + (size_t)row * DMODEL + c * 8);
            cpa16(sb + AT_Q + 16384 + soff, Qlo + qgb + (size_t)row * DMODEL + c * 8);
        }
    }
    CP_COMMIT();

    float o[8][4];
#pragma unroll
    for (int nt = 0; nt < 8; nt++)
#pragma unroll
        for (int r = 0; r < 4; r++) o[nt][r] = 0.f;
    float m[2] = {-1e30f, -1e30f};
    float l[2] = {0.f, 0.f};

    const int qw = qb * 128 + wid * 16;
    const int r0 = lane >> 2, c0 = (lane & 3) * 2;
    const int ra = lane & 15, ca = lane >> 4;
    const int jb_off = (lane >> 4) & 1;      // which tile of the ldsm_x4 pair
    const int kb_half = (lane >> 3) & 1;     // k-half within the pair
    const int rb = lane & 7;
    const int last = 2 * qb + 1;

    att_load_kv(Khi, Klo, Vf, b, h, 0, sb + AT_STG0, tid);
    CP_COMMIT();

    for (int kb = 0; kb <= last; kb++) {
        if (kb < last) {
            att_load_kv(Khi, Klo, Vf, b, h, kb + 1,
                        sb + AT_STG0 + ((kb + 1) & 1) * AT_STGB, tid);
            CP_COMMIT();
            CP_WAIT1();
        } else {
            CP_WAIT0();
        }
        __syncthreads();

        const int avail = qw + 15 - kb * 64;
        if (avail >= 0) {
            const uint32_t stg = sb + AT_STG0 + (kb & 1) * AT_STGB;
            const int ntS  = min(8, (avail >> 3) + 1);
            const int ksPV = min(4, (avail >> 4) + 1);

            float s[8][4];
#pragma unroll
            for (int nt = 0; nt < 8; nt++)
#pragma unroll
                for (int r = 0; r < 4; r++) s[nt][r] = 0.f;

#pragma unroll
            for (int ks = 0; ks < 4; ks++) {
                uint32_t ah[4], al[4];
                int arow = wid * 16 + ra;
                int ach = (ks * 2 + ca) ^ (arow & 7);
                uint32_t ad = sb + AT_Q + arow * 128 + ach * 16;
                ldsm_x4(ah, ad);
                ldsm_x4(al, ad + 16384);
#pragma unroll
                for (int g = 0; g < 2; g++) {
                    const int nt0 = g * 4;
                    if (nt0 < ntS) {
                        uint32_t bhf[4][2], blf[4][2];
#pragma unroll
                        for (int np = 0; np < 2; np++) {
                            if (nt0 + np * 2 < ntS) {
                                int brow = (nt0 + np * 2 + jb_off) * 8 + rb;
                                int bch = (ks * 2 + kb_half) ^ (brow & 7);
                                uint32_t bd = stg + brow * 128 + bch * 16;
                                ldsm_x4(bhf[np * 2], bd);
                                ldsm_x4(blf[np * 2], bd + 8192);
                            }
                        }
#pragma unroll
                        for (int j = 0; j < 4; j++)
                            if (nt0 + j < ntS) mma_bf16(s[nt0 + j], ah, bhf[j]);
#pragma unroll
                        for (int j = 0; j < 4; j++)
                            if (nt0 + j < ntS) mma_bf16(s[nt0 + j], ah, blf[j]);
#pragma unroll
                        for (int j = 0; j < 4; j++)
                            if (nt0 + j < ntS) mma_bf16(s[nt0 + j], al, bhf[j]);
                    }
                }
            }

            if (kb * 64 + 63 > qw) {
#pragma unroll
                for (int nt = 0; nt < 8; nt++) {
#pragma unroll
                    for (int v = 0; v < 4; v++) {
                        int kg = kb * 64 + nt * 8 + c0 + (v & 1);
                        int qg = qw + r0 + ((v >> 1) << 3);
                        if (kg > qg) s[nt][v] = -1e30f;
                    }
                }
            }

#pragma unroll
            for (int hf = 0; hf < 2; hf++) {
                float mx = -1e30f;
#pragma unroll
                for (int nt = 0; nt < 8; nt++)
                    mx = fmaxf(mx, fmaxf(s[nt][hf * 2], s[nt][hf * 2 + 1]));
                mx = fmaxf(mx, __shfl_xor_sync(0xffffffffu, mx, 1));
                mx = fmaxf(mx, __shfl_xor_sync(0xffffffffu, mx, 2));
                const float mn = fmaxf(m[hf], mx);
                const float sc = __expf(m[hf] - mn);
                float rs = 0.f;
#pragma unroll
                for (int nt = 0; nt < 8; nt++) {
                    float e0 = __expf(s[nt][hf * 2] - mn);
                    float e1 = __expf(s[nt][hf * 2 + 1] - mn);
                    s[nt][hf * 2] = e0;
                    s[nt][hf * 2 + 1] = e1;
                    rs += e0 + e1;
                }
                rs += __shfl_xor_sync(0xffffffffu, rs, 1);
                rs += __shfl_xor_sync(0xffffffffu, rs, 2);
                l[hf] = l[hf] * sc + rs;
                m[hf] = mn;
#pragma unroll
                for (int nt = 0; nt < 8; nt++) {
                    o[nt][hf * 2] *= sc;
                    o[nt][hf * 2 + 1] *= sc;
                }
            }

            // ---- O += P @ V: P exact fp16 split, V fp16, 2 passes ----
#pragma unroll
            for (int ks = 0; ks < 4; ks++) {
                if (ks < ksPV) {
                    uint32_t phi[4], plo[4];
#pragma unroll
                    for (int t2 = 0; t2 < 2; t2++) {
                        const float* sv = s[ks * 2 + t2];
                        float h0 = __half2float(__float2half(sv[0]));
                        float h1 = __half2float(__float2half(sv[1]));
                        float h2 = __half2float(__float2half(sv[2]));
                        float h3 = __half2float(__float2half(sv[3]));
                        phi[t2 * 2 + 0] = packh(h0, h1);
                        phi[t2 * 2 + 1] = packh(h2, h3);
                        plo[t2 * 2 + 0] = packh(sv[0] - h0, sv[1] - h1);
                        plo[t2 * 2 + 1] = packh(sv[2] - h2, sv[3] - h3);
                    }
#pragma unroll
                    for (int g = 0; g < 2; g++) {
                        const int nt0 = g * 4;
                        uint32_t vhf[4][2];
#pragma unroll
                        for (int np = 0; np < 2; np++) {
                            int krow = ks * 16 + kb_half * 8 + rb;        // key row
                            int dch = nt0 + np * 2 + jb_off;              // d chunk
                            int bch = dch ^ (krow & 7);
                            uint32_t bd = stg + AT_VOFF + krow * 128 + bch * 16;
                            ldsm_x4t(vhf[np * 2], bd);
                        }
#pragma unroll
                        for (int j = 0; j < 4; j++)
                            mma_f16(o[nt0 + j], phi, vhf[j]);
#pragma unroll
                        for (int j = 0; j < 4; j++)
                            mma_f16(o[nt0 + j], plo, vhf[j]);
                    }
                }
            }
        }
        __syncthreads();
    }

    // epilogue: att = O / l * 0.125, rounded to single fp16
    const float inv0 = 0.125f / l[0];
    const float inv1 = 0.125f / l[1];
    const size_t row0 = (size_t)(b * SEQL + qw + r0);
#pragma unroll
    for (int nt = 0; nt < 8; nt++) {
        const int col = h * DHEAD + nt * 8 + c0;
        size_t o0 = row0 * DMODEL + col;
        size_t o1 = (row0 + 8) * DMODEL + col;
        *(uint32_t*)(Oatt + o0) = packh(o[nt][0] * inv0, o[nt][1] * inv0);
        *(uint32_t*)(Oatt + o1) = packh(o[nt][2] * inv1, o[nt][3] * inv1);
    }
}

// ---------------------------------------------------------------------------
// Launch
// ---------------------------------------------------------------------------
extern "C" void kernel_launch(void* const* d_in, const int* in_sizes, int n_in,
                              void* d_out, int out_size) {
    const float* q  = (const float*)d_in[0];
    const float* k  = (const float*)d_in[1];
    const float* v  = (const float*)d_in[2];
    const float* Wq = (const float*)d_in[4];
    const float* Wk = (const float*)d_in[5];
    const float* Wv = (const float*)d_in[6];
    const float* Wo = (const float*)d_in[7];
    float* out = (float*)d_out;

    void *pi3h, *pi3l, *pw4h, *pqh, *pql, *pkh, *pkl, *pvf, *pat;
    cudaGetSymbolAddress(&pi3h, g_in3hi);
    cudaGetSymbolAddress(&pi3l, g_in3lo);
    cudaGetSymbolAddress(&pw4h, g_w4hi);
    cudaGetSymbolAddress(&pqh, g_qhi);
    cudaGetSymbolAddress(&pql, g_qlo);
    cudaGetSymbolAddress(&pkh, g_khi);
    cudaGetSymbolAddress(&pkl, g_klo);
    cudaGetSymbolAddress(&pvf, g_vf);
    cudaGetSymbolAddress(&pat, g_att);

    __half* i3h = (__half*)pi3h;
    __half* i3l = (__half*)pi3l;
    __half* w4h = (__half*)pw4h;
    const size_t WS = (size_t)DMODEL * DMODEL;

    cudaFuncSetAttribute(gemm_qkv, cudaFuncAttributeMaxDynamicSharedMemorySize, SMEM_GEMM);
    cudaFuncSetAttribute(gemm_wo,  cudaFuncAttributeMaxDynamicSharedMemorySize, SMEM_GEMM);
    cudaFuncSetAttribute(attn_tc, cudaFuncAttributeMaxDynamicSharedMemorySize, SMEM_ATT);

    const int n4 = (BLROWS * DMODEL) / 4;
    const dim3 tb(32, 8);

    split3<<<dim3((n4 / 4 + 255) / 256, 1, 3), 256>>>(q, k, v, i3h, i3l, n4);
    splitT4<<<dim3(32, 32, 4), tb>>>(Wq, Wk, Wv, Wo, w4h);

    gemm_qkv<<<dim3(DMODEL / 128, BLROWS / 128, 3), GEMM_THREADS, SMEM_GEMM>>>(
        i3h, i3l, w4h,
        (__nv_bfloat16*)pqh, (__nv_bfloat16*)pql,
        (__nv_bfloat16*)pkh, (__nv_bfloat16*)pkl, (__half*)pvf);

    attn_tc<<<dim3(NHEAD * BATCH, SEQL / 128, 1), 256, SMEM_ATT>>>(
        (const __nv_bfloat16*)pqh, (const __nv_bfloat16*)pql,
        (const __nv_bfloat16*)pkh, (const __nv_bfloat16*)pkl,
        (const __half*)pvf, (__half*)pat);

    gemm_wo<<<dim3(DMODEL / 128, BLROWS / 128), GEMM_THREADS, SMEM_GEMM>>>(
        (const __half*)pat, w4h + 3 * WS, out);
}

// round 17
// speedup vs baseline: 1.2289x; 1.0814x over previous
#include <cuda_runtime.h>
#include <cuda_bf16.h>
#include <cuda_fp16.h>
#include <cstdint>

// Problem constants
#define BATCH 2
#define SEQL  2048
#define DMODEL 1024
#define NHEAD 16
#define DHEAD 64
#define BLROWS (BATCH * SEQL)   // 4096
#define GK 1024

// ---------------------------------------------------------------------------
// Scratch
// ---------------------------------------------------------------------------
__device__ __half g_in3hi[(size_t)3 * BLROWS * DMODEL];                 // q,k,v split (fp16)
__device__ __half g_in3lo[(size_t)3 * BLROWS * DMODEL];                 // lo for q,k only
__device__ __half g_w4hi[(size_t)4 * DMODEL * DMODEL];                  // W^T rounded fp16
__device__ __nv_bfloat16 g_qhi[(size_t)BLROWS * DMODEL];
__device__ __nv_bfloat16 g_qlo[(size_t)BLROWS * DMODEL];
__device__ __nv_bfloat16 g_khi[(size_t)BLROWS * DMODEL];
__device__ __nv_bfloat16 g_klo[(size_t)BLROWS * DMODEL];
__device__ __half g_vf[(size_t)BLROWS * DMODEL];                        // V proj, fp16, token-major
__device__ __half g_att[(size_t)BLROWS * DMODEL];                       // attention out (fp16)

// ---------------------------------------------------------------------------
// PTX helpers
// ---------------------------------------------------------------------------
__device__ __forceinline__ uint32_t s2u(const void* p) {
    uint32_t a;
    asm("{ .reg .u64 t; cvta.to.shared.u64 t, %1; cvt.u32.u64 %0, t; }"
        : "=r"(a) : "l"(p));
    return a;
}
__device__ __forceinline__ void ldsm_x4(uint32_t* r, uint32_t addr) {
    asm volatile("ldmatrix.sync.aligned.m8n8.x4.shared.b16 {%0,%1,%2,%3}, [%4];"
                 : "=r"(r[0]), "=r"(r[1]), "=r"(r[2]), "=r"(r[3]) : "r"(addr));
}
__device__ __forceinline__ void ldsm_x4t(uint32_t* r, uint32_t addr) {
    asm volatile("ldmatrix.sync.aligned.m8n8.x4.trans.shared.b16 {%0,%1,%2,%3}, [%4];"
                 : "=r"(r[0]), "=r"(r[1]), "=r"(r[2]), "=r"(r[3]) : "r"(addr));
}
// bf16 mma (attention S)
__device__ __forceinline__ void mma_bf16(float* d, const uint32_t* a, const uint32_t* b) {
    asm volatile("mma.sync.aligned.m16n8k16.row.col.f32.bf16.bf16.f32 "
                 "{%0,%1,%2,%3}, {%4,%5,%6,%7}, {%8,%9}, {%0,%1,%2,%3};"
                 : "+f"(d[0]), "+f"(d[1]), "+f"(d[2]), "+f"(d[3])
                 : "r"(a[0]), "r"(a[1]), "r"(a[2]), "r"(a[3]), "r"(b[0]), "r"(b[1]));
}
// fp16 mma (projection GEMMs + attention PV)
__device__ __forceinline__ void mma_f16(float* d, const uint32_t* a, const uint32_t* b) {
    asm volatile("mma.sync.aligned.m16n8k16.row.col.f32.f16.f16.f32 "
                 "{%0,%1,%2,%3}, {%4,%5,%6,%7}, {%8,%9}, {%0,%1,%2,%3};"
                 : "+f"(d[0]), "+f"(d[1]), "+f"(d[2]), "+f"(d[3])
                 : "r"(a[0]), "r"(a[1]), "r"(a[2]), "r"(a[3]), "r"(b[0]), "r"(b[1]));
}
__device__ __forceinline__ void cpa16(uint32_t saddr, const void* g) {
    asm volatile("cp.async.cg.shared.global [%0], [%1], 16;" :: "r"(saddr), "l"(g));
}
#define CP_COMMIT() asm volatile("cp.async.commit_group;" ::: "memory")
#define CP_WAIT1()  asm volatile("cp.async.wait_group 1;" ::: "memory")
#define CP_WAIT0()  asm volatile("cp.async.wait_group 0;" ::: "memory")

__device__ __forceinline__ uint32_t packbf(float lo, float hi) {
    uint32_t d;
    asm("cvt.rn.bf16x2.f32 %0, %1, %2;" : "=r"(d) : "f"(hi), "f"(lo));
    return d;
}
__device__ __forceinline__ uint32_t packh(float lo, float hi) {
    uint32_t d;
    asm("cvt.rn.f16x2.f32 %0, %1, %2;" : "=r"(d) : "f"(hi), "f"(lo));
    return d;
}

// ---------------------------------------------------------------------------
// Conversion kernels
// ---------------------------------------------------------------------------
// q,k,v fp32 -> fp16 hi (+lo for q,k only). 4 coalesced float4 per thread.
__global__ __launch_bounds__(256) void split3(const float* __restrict__ q,
                                              const float* __restrict__ k,
                                              const float* __restrict__ v,
                                              __half* __restrict__ hi,
                                              __half* __restrict__ lo,
                                              int n4) {
    const int base = blockIdx.x * 1024 + threadIdx.x;
    const int z = blockIdx.z;
    const float* in = (z == 0) ? q : (z == 1) ? k : v;
    const size_t off = (size_t)z * BLROWS * DMODEL / 2;   // half2 units
    float4 val[4];
#pragma unroll
    for (int t = 0; t < 4; t++) {
        int i = base + t * 256;
        if (i < n4) val[t] = ((const float4*)in)[i];
    }
#pragma unroll
    for (int t = 0; t < 4; t++) {
        const int i = base + t * 256;
        if (i < n4) {
            __half h0 = __float2half(val[t].x);
            __half h1 = __float2half(val[t].y);
            __half h2 = __float2half(val[t].z);
            __half h3 = __float2half(val[t].w);
            ((__half2*)hi)[off + 2 * i]     = __halves2half2(h0, h1);
            ((__half2*)hi)[off + 2 * i + 1] = __halves2half2(h2, h3);
            if (z < 2) {   // lo residual only needed for Q,K (2-pass GEMMs)
                __half l0 = __float2half(val[t].x - __half2float(h0));
                __half l1 = __float2half(val[t].y - __half2float(h1));
                __half l2 = __float2half(val[t].z - __half2float(h2));
                __half l3 = __float2half(val[t].w - __half2float(h3));
                ((__half2*)lo)[off + 2 * i]     = __halves2half2(l0, l1);
                ((__half2*)lo)[off + 2 * i + 1] = __halves2half2(l2, l3);
            }
        }
    }
}

// W [K][N] fp32 -> Wt [N][K] fp16 (transposed, rounded), all four weights.
__global__ __launch_bounds__(256) void splitT4(const float* __restrict__ w0,
                                               const float* __restrict__ w1,
                                               const float* __restrict__ w2,
                                               const float* __restrict__ w3,
                                               __half* __restrict__ th) {
    __shared__ float t[32][33];
    const int tx = threadIdx.x, ty = threadIdx.y;
    const int n0 = blockIdx.x * 32, k0 = blockIdx.y * 32;
    const int z = blockIdx.z;
    const float* W = (z == 0) ? w0 : (z == 1) ? w1 : (z == 2) ? w2 : w3;
    const size_t zoff = (size_t)z * DMODEL * DMODEL;
#pragma unroll
    for (int i = 0; i < 32; i += 8)
        t[ty + i][tx] = W[(size_t)(k0 + ty + i) * DMODEL + n0 + tx];
    __syncthreads();
#pragma unroll
    for (int i = 0; i < 32; i += 8) {
        float x = t[tx][ty + i];
        th[zoff + (size_t)(n0 + ty + i) * DMODEL + k0 + tx] = __float2half(x);
    }
}

// ---------------------------------------------------------------------------
// fp16 GEMM: C = (A_hi [+ A_lo]) @ B  (TWO=true: 2-pass exact-A; false: 1-pass)
// 128x128 block, 4 warps (64x64 warp tiles), 3-stage pipeline, K-chunk 32.
// Epilogue mode: 0 = fp32, 1 = bf16 hi/lo split, 2 = fp16 rounded.
// ---------------------------------------------------------------------------
#define GBUF   8192u                 // one 128x32 fp16 tile
#define GSTG   24576u                // 3 tiles per stage (2-pass layout)
#define SMEM_GEMM (3u * GSTG)        // 73728
#define GEMM_THREADS 128

template <bool TWO>
__device__ __forceinline__ void stage_load32(const __half* __restrict__ Ahi,
                                             const __half* __restrict__ Alo,
                                             const __half* __restrict__ B,
                                             int am0, int bn0, int k0,
                                             uint32_t sbase, int tid) {
#pragma unroll
    for (int b = 0; b < 3; b++) {
        if (!TWO && b == 1) continue;
        const __half* g = (b == 0) ? Ahi : (b == 1) ? Alo : B;
        const int r0 = (b < 2) ? am0 : bn0;
        const uint32_t sbuf = sbase + b * GBUF;
#pragma unroll
        for (int t = 0; t < 4; t++) {
            int u = tid + t * GEMM_THREADS;
            int row = u >> 2, c = u & 3;
            int sw = c ^ ((row >> 1) & 3);
            cpa16(sbuf + row * 64 + sw * 16,
                  g + (size_t)(r0 + row) * GK + k0 + c * 8);
        }
    }
}

template <bool TWO>
__device__ __forceinline__ void gemm_body(const __half* __restrict__ Ahi,
                                          const __half* __restrict__ Alo,
                                          const __half* __restrict__ B,
                                          float* __restrict__ C,
                                          __nv_bfloat16* __restrict__ Chi,
                                          __nv_bfloat16* __restrict__ Clo,
                                          __half* __restrict__ Ch,
                                          int N, int mode, uint32_t sb,
                                          int bm, int bn) {
    const int tid = threadIdx.x;
    const int wid = tid >> 5, lane = tid & 31;
    const int wm = wid & 1;          // 64-row slab
    const int wn = wid >> 1;         // 64-col slab
    const int am0 = bm * 128, bn0 = bn * 128;

    float acc[4][8][4];
#pragma unroll
    for (int i = 0; i < 4; i++)
#pragma unroll
        for (int j = 0; j < 8; j++)
#pragma unroll
            for (int r = 0; r < 4; r++) acc[i][j][r] = 0.f;

    const int NC = GK / 32;          // 32 chunks
    stage_load32<TWO>(Ahi, Alo, B, am0, bn0, 0, sb, tid);
    CP_COMMIT();
    stage_load32<TWO>(Ahi, Alo, B, am0, bn0, 32, sb + GSTG, tid);
    CP_COMMIT();

    const int ra = lane & 15, ca = lane >> 4;
    const int jb_off = (lane >> 4) & 1;
    const int kb_half = (lane >> 3) & 1;
    const int rb = lane & 7;
    int stg = 0;
    for (int c = 0; c < NC; c++) {
        if (c < NC - 1) CP_WAIT1(); else CP_WAIT0();
        __syncthreads();

        const uint32_t base = sb + stg * GSTG;
#pragma unroll
        for (int ks = 0; ks < 2; ks++) {
            uint32_t ah[4][4], al[4][4];
#pragma unroll
            for (int i = 0; i < 4; i++) {
                int row = wm * 64 + i * 16 + ra;
                int ch = (ks * 2 + ca) ^ ((row >> 1) & 3);
                uint32_t ad = base + row * 64 + ch * 16;
                ldsm_x4(ah[i], ad);
                if (TWO) ldsm_x4(al[i], ad + GBUF);
            }
            uint32_t bh[8][2];
#pragma unroll
            for (int jp = 0; jp < 4; jp++) {
                int row = wn * 64 + (jp * 2 + jb_off) * 8 + rb;
                int ch = (ks * 2 + kb_half) ^ ((row >> 1) & 3);
                uint32_t bd = base + 2 * GBUF + row * 64 + ch * 16;
                ldsm_x4(bh[jp * 2], bd);
            }
#pragma unroll
            for (int i = 0; i < 4; i++)
#pragma unroll
                for (int j = 0; j < 8; j++)
                    mma_f16(acc[i][j], ah[i], bh[j]);
            if (TWO) {
#pragma unroll
                for (int i = 0; i < 4; i++)
#pragma unroll
                    for (int j = 0; j < 8; j++)
                        mma_f16(acc[i][j], al[i], bh[j]);
            }
        }

        if (c + 2 < NC) {
            stage_load32<TWO>(Ahi, Alo, B, am0, bn0, (c + 2) * 32,
                              sb + ((stg + 2) % 3) * GSTG, tid);
            CP_COMMIT();
        }
        stg = (stg + 1) % 3;
    }

    const int r0 = lane >> 2, c0 = (lane & 3) * 2;
#pragma unroll
    for (int i = 0; i < 4; i++) {
#pragma unroll
        for (int j = 0; j < 8; j++) {
            const int grow = am0 + wm * 64 + i * 16 + r0;
            const int gcol = bn0 + wn * 64 + j * 8 + c0;
            if (mode == 0) {
                float2 v0 = {acc[i][j][0], acc[i][j][1]};
                float2 v1 = {acc[i][j][2], acc[i][j][3]};
                *(float2*)(C + (size_t)grow * N + gcol)       = v0;
                *(float2*)(C + (size_t)(grow + 8) * N + gcol) = v1;
            } else if (mode == 1) {
#pragma unroll
                for (int half = 0; half < 2; half++) {
                    float a0 = acc[i][j][half * 2], a1 = acc[i][j][half * 2 + 1];
                    float h0 = __bfloat162float(__float2bfloat16(a0));
                    float h1 = __bfloat162float(__float2bfloat16(a1));
                    size_t o = (size_t)(grow + half * 8) * N + gcol;
                    *(uint32_t*)(Chi + o) = packbf(h0, h1);
                    *(uint32_t*)(Clo + o) = packbf(a0 - h0, a1 - h1);
                }
            } else {
#pragma unroll
                for (int half = 0; half < 2; half++) {
                    size_t o = (size_t)(grow + half * 8) * N + gcol;
                    *(uint32_t*)(Ch + o) = packh(acc[i][j][half * 2],
                                                 acc[i][j][half * 2 + 1]);
                }
            }
        }
    }
}

// Q/K projections (2-pass, bf16 hi/lo out): grid (8, 32, 2)
__global__ __launch_bounds__(GEMM_THREADS, 2) void gemm_qk(const __half* __restrict__ i3h,
                                                           const __half* __restrict__ i3l,
                                                           const __half* __restrict__ w4h,
                                                           __nv_bfloat16* __restrict__ qhi,
                                                           __nv_bfloat16* __restrict__ qlo,
                                                           __nv_bfloat16* __restrict__ khi,
                                                           __nv_bfloat16* __restrict__ klo) {
    extern __shared__ char sm[];
    const uint32_t sb = s2u(sm);
    const int z = blockIdx.z;
    const size_t IS = (size_t)BLROWS * DMODEL;
    const size_t WS = (size_t)DMODEL * DMODEL;
    __nv_bfloat16* Chi = (z == 0) ? qhi : khi;
    __nv_bfloat16* Clo = (z == 0) ? qlo : klo;
    gemm_body<true>(i3h + (size_t)z * IS, i3l + (size_t)z * IS, w4h + (size_t)z * WS,
                    nullptr, Chi, Clo, nullptr, DMODEL, 1, sb,
                    blockIdx.y, blockIdx.x);
}

// V projection (1-pass: fp16(v) @ fp16(Wv), fp16 out): grid (8, 32)
__global__ __launch_bounds__(GEMM_THREADS, 2) void gemm_v(const __half* __restrict__ vh16,
                                                          const __half* __restrict__ wv,
                                                          __half* __restrict__ vf) {
    extern __shared__ char sm[];
    const uint32_t sb = s2u(sm);
    gemm_body<false>(vh16, nullptr, wv, nullptr, nullptr, nullptr, vf, DMODEL, 2, sb,
                     blockIdx.y, blockIdx.x);
}

// Wo projection: single-pass (A = rounded fp16 att), fp32 out.
__global__ __launch_bounds__(GEMM_THREADS, 2) void gemm_wo(const __half* __restrict__ A,
                                                           const __half* __restrict__ B,
                                                           float* __restrict__ C) {
    extern __shared__ char sm[];
    const uint32_t sb = s2u(sm);
    gemm_body<false>(A, nullptr, B, C, nullptr, nullptr, nullptr, DMODEL, 0, sb,
                     blockIdx.y, blockIdx.x);
}

// ---------------------------------------------------------------------------
// Tensor-core causal flash attention.
// S: bf16 3-pass (Qhi/Qlo x Khi/Klo). PV: fp16 2-pass (P exact split x fp16 V).
// Tree-reduced softmax (shorter dependency chain).
// ---------------------------------------------------------------------------
#define AT_Q    0u
#define AT_STG0 32768u
#define AT_STGB 24576u
#define AT_VOFF 16384u
#define SMEM_ATT (AT_STG0 + 2u * AT_STGB)   // 81920

__device__ __forceinline__ void att_load_kv(const __nv_bfloat16* __restrict__ Khi,
                                            const __nv_bfloat16* __restrict__ Klo,
                                            const __half* __restrict__ Vf,
                                            int b, int h, int kb,
                                            uint32_t stg, int tid) {
    const size_t gb = (size_t)(b * SEQL + kb * 64) * DMODEL + h * DHEAD;
#pragma unroll
    for (int t = 0; t < 2; t++) {
        int u = tid + t * 256;
        int row = u >> 3, c = u & 7;
        uint32_t soff = row * 128 + ((c ^ (row & 7)) * 16);
        const size_t goff = gb + (size_t)row * DMODEL + c * 8;
        cpa16(stg + soff,            Khi + goff);
        cpa16(stg + 8192 + soff,     Klo + goff);
        cpa16(stg + AT_VOFF + soff,  Vf + goff);
    }
}

__global__ __launch_bounds__(256, 2) void attn_tc(const __nv_bfloat16* __restrict__ Qhi,
                                                  const __nv_bfloat16* __restrict__ Qlo,
                                                  const __nv_bfloat16* __restrict__ Khi,
                                                  const __nv_bfloat16* __restrict__ Klo,
                                                  const __half* __restrict__ Vf,
                                                  __half* __restrict__ Oatt) {
    extern __shared__ char sm[];
    const uint32_t sb = s2u(sm);
    const int tid = threadIdx.x;
    const int wid = tid >> 5, lane = tid & 31;
    const int qb = (int)gridDim.y - 1 - (int)blockIdx.y;   // heavy tiles first
    const int h = blockIdx.x & 15, b = blockIdx.x >> 4;

    {
        const size_t qgb = (size_t)(b * SEQL + qb * 128) * DMODEL + h * DHEAD;
#pragma unroll
        for (int t = 0; t < 4; t++) {
            int u = tid + t * 256;
            int row = u >> 3, c = u & 7;
            uint32_t soff = row * 128 + ((c ^ (row & 7)) * 16);
            cpa16(sb + AT_Q + soff,         Qhi + qgb + (size_t)row * DMODEL + c * 8);
            cpa16(sb + AT_Q + 16384 + soff, Qlo + qgb + (size_t)row * DMODEL + c * 8);
        }
    }
    CP_COMMIT();

    float o[8][4];
#pragma unroll
    for (int nt = 0; nt < 8; nt++)
#pragma unroll
        for (int r = 0; r < 4; r++) o[nt][r] = 0.f;
    float m[2] = {-1e30f, -1e30f};
    float l[2] = {0.f, 0.f};

    const int qw = qb * 128 + wid * 16;
    const int r0 = lane >> 2, c0 = (lane & 3) * 2;
    const int ra = lane & 15, ca = lane >> 4;
    const int jb_off = (lane >> 4) & 1;      // which tile of the ldsm_x4 pair
    const int kb_half = (lane >> 3) & 1;     // k-half within the pair
    const int rb = lane & 7;
    const int last = 2 * qb + 1;

    att_load_kv(Khi, Klo, Vf, b, h, 0, sb + AT_STG0, tid);
    CP_COMMIT();

    for (int kb = 0; kb <= last; kb++) {
        if (kb < last) {
            att_load_kv(Khi, Klo, Vf, b, h, kb + 1,
                        sb + AT_STG0 + ((kb + 1) & 1) * AT_STGB, tid);
            CP_COMMIT();
            CP_WAIT1();
        } else {
            CP_WAIT0();
        }
        __syncthreads();

        const int avail = qw + 15 - kb * 64;
        if (avail >= 0) {
            const uint32_t stg = sb + AT_STG0 + (kb & 1) * AT_STGB;
            const int ntS  = min(8, (avail >> 3) + 1);
            const int ksPV = min(4, (avail >> 4) + 1);

            float s[8][4];
#pragma unroll
            for (int nt = 0; nt < 8; nt++)
#pragma unroll
                for (int r = 0; r < 4; r++) s[nt][r] = 0.f;

#pragma unroll
            for (int ks = 0; ks < 4; ks++) {
                uint32_t ah[4], al[4];
                int arow = wid * 16 + ra;
                int ach = (ks * 2 + ca) ^ (arow & 7);
                uint32_t ad = sb + AT_Q + arow * 128 + ach * 16;
                ldsm_x4(ah, ad);
                ldsm_x4(al, ad + 16384);
#pragma unroll
                for (int g = 0; g < 2; g++) {
                    const int nt0 = g * 4;
                    if (nt0 < ntS) {
                        uint32_t bhf[4][2], blf[4][2];
#pragma unroll
                        for (int np = 0; np < 2; np++) {
                            if (nt0 + np * 2 < ntS) {
                                int brow = (nt0 + np * 2 + jb_off) * 8 + rb;
                                int bch = (ks * 2 + kb_half) ^ (brow & 7);
                                uint32_t bd = stg + brow * 128 + bch * 16;
                                ldsm_x4(bhf[np * 2], bd);
                                ldsm_x4(blf[np * 2], bd + 8192);
                            }
                        }
#pragma unroll
                        for (int j = 0; j < 4; j++)
                            if (nt0 + j < ntS) mma_bf16(s[nt0 + j], ah, bhf[j]);
#pragma unroll
                        for (int j = 0; j < 4; j++)
                            if (nt0 + j < ntS) mma_bf16(s[nt0 + j], ah, blf[j]);
#pragma unroll
                        for (int j = 0; j < 4; j++)
                            if (nt0 + j < ntS) mma_bf16(s[nt0 + j], al, bhf[j]);
                    }
                }
            }

            if (kb * 64 + 63 > qw) {
#pragma unroll
                for (int nt = 0; nt < 8; nt++) {
#pragma unroll
                    for (int v = 0; v < 4; v++) {
                        int kg = kb * 64 + nt * 8 + c0 + (v & 1);
                        int qg = qw + r0 + ((v >> 1) << 3);
                        if (kg > qg) s[nt][v] = -1e30f;
                    }
                }
            }

            // ---- online softmax, tree-reduced ----
#pragma unroll
            for (int hf = 0; hf < 2; hf++) {
                const int h2 = hf * 2;
                // row max: 3-level tree
                float t0 = fmaxf(fmaxf(s[0][h2], s[0][h2 + 1]), fmaxf(s[1][h2], s[1][h2 + 1]));
                float t1 = fmaxf(fmaxf(s[2][h2], s[2][h2 + 1]), fmaxf(s[3][h2], s[3][h2 + 1]));
                float t2 = fmaxf(fmaxf(s[4][h2], s[4][h2 + 1]), fmaxf(s[5][h2], s[5][h2 + 1]));
                float t3 = fmaxf(fmaxf(s[6][h2], s[6][h2 + 1]), fmaxf(s[7][h2], s[7][h2 + 1]));
                float mx = fmaxf(fmaxf(t0, t1), fmaxf(t2, t3));
                mx = fmaxf(mx, __shfl_xor_sync(0xffffffffu, mx, 1));
                mx = fmaxf(mx, __shfl_xor_sync(0xffffffffu, mx, 2));
                const float mn = fmaxf(m[hf], mx);
                const float sc = __expf(m[hf] - mn);
#pragma unroll
                for (int nt = 0; nt < 8; nt++) {
                    s[nt][h2]     = __expf(s[nt][h2] - mn);
                    s[nt][h2 + 1] = __expf(s[nt][h2 + 1] - mn);
                }
                // exp sum: pairwise tree
                float r0s = (s[0][h2] + s[0][h2 + 1]) + (s[1][h2] + s[1][h2 + 1]);
                float r1s = (s[2][h2] + s[2][h2 + 1]) + (s[3][h2] + s[3][h2 + 1]);
                float r2s = (s[4][h2] + s[4][h2 + 1]) + (s[5][h2] + s[5][h2 + 1]);
                float r3s = (s[6][h2] + s[6][h2 + 1]) + (s[7][h2] + s[7][h2 + 1]);
                float rs = (r0s + r1s) + (r2s + r3s);
                rs += __shfl_xor_sync(0xffffffffu, rs, 1);
                rs += __shfl_xor_sync(0xffffffffu, rs, 2);
                l[hf] = l[hf] * sc + rs;
                m[hf] = mn;
#pragma unroll
                for (int nt = 0; nt < 8; nt++) {
                    o[nt][h2]     *= sc;
                    o[nt][h2 + 1] *= sc;
                }
            }

            // ---- O += P @ V: P exact fp16 split, V fp16, 2 passes ----
#pragma unroll
            for (int ks = 0; ks < 4; ks++) {
                if (ks < ksPV) {
                    uint32_t phi[4], plo[4];
#pragma unroll
                    for (int t2 = 0; t2 < 2; t2++) {
                        const float* sv = s[ks * 2 + t2];
                        float h0 = __half2float(__float2half(sv[0]));
                        float h1 = __half2float(__float2half(sv[1]));
                        float h2 = __half2float(__float2half(sv[2]));
                        float h3 = __half2float(__float2half(sv[3]));
                        phi[t2 * 2 + 0] = packh(h0, h1);
                        phi[t2 * 2 + 1] = packh(h2, h3);
                        plo[t2 * 2 + 0] = packh(sv[0] - h0, sv[1] - h1);
                        plo[t2 * 2 + 1] = packh(sv[2] - h2, sv[3] - h3);
                    }
#pragma unroll
                    for (int g = 0; g < 2; g++) {
                        const int nt0 = g * 4;
                        uint32_t vhf[4][2];
#pragma unroll
                        for (int np = 0; np < 2; np++) {
                            int krow = ks * 16 + kb_half * 8 + rb;        // key row
                            int dch = nt0 + np * 2 + jb_off;              // d chunk
                            int bch = dch ^ (krow & 7);
                            uint32_t bd = stg + AT_VOFF + krow * 128 + bch * 16;
                            ldsm_x4t(vhf[np * 2], bd);
                        }
#pragma unroll
                        for (int j = 0; j < 4; j++)
                            mma_f16(o[nt0 + j], phi, vhf[j]);
#pragma unroll
                        for (int j = 0; j < 4; j++)
                            mma_f16(o[nt0 + j], plo, vhf[j]);
                    }
                }
            }
        }
        __syncthreads();
    }

    // epilogue: att = O / l * 0.125, rounded to single fp16
    const float inv0 = 0.125f / l[0];
    const float inv1 = 0.125f / l[1];
    const size_t row0 = (size_t)(b * SEQL + qw + r0);
#pragma unroll
    for (int nt = 0; nt < 8; nt++) {
        const int col = h * DHEAD + nt * 8 + c0;
        size_t o0 = row0 * DMODEL + col;
        size_t o1 = (row0 + 8) * DMODEL + col;
        *(uint32_t*)(Oatt + o0) = packh(o[nt][0] * inv0, o[nt][1] * inv0);
        *(uint32_t*)(Oatt + o1) = packh(o[nt][2] * inv1, o[nt][3] * inv1);
    }
}

// ---------------------------------------------------------------------------
// Launch
// ---------------------------------------------------------------------------
extern "C" void kernel_launch(void* const* d_in, const int* in_sizes, int n_in,
                              void* d_out, int out_size) {
    const float* q  = (const float*)d_in[0];
    const float* k  = (const float*)d_in[1];
    const float* v  = (const float*)d_in[2];
    const float* Wq = (const float*)d_in[4];
    const float* Wk = (const float*)d_in[5];
    const float* Wv = (const float*)d_in[6];
    const float* Wo = (const float*)d_in[7];
    float* out = (float*)d_out;

    void *pi3h, *pi3l, *pw4h, *pqh, *pql, *pkh, *pkl, *pvf, *pat;
    cudaGetSymbolAddress(&pi3h, g_in3hi);
    cudaGetSymbolAddress(&pi3l, g_in3lo);
    cudaGetSymbolAddress(&pw4h, g_w4hi);
    cudaGetSymbolAddress(&pqh, g_qhi);
    cudaGetSymbolAddress(&pql, g_qlo);
    cudaGetSymbolAddress(&pkh, g_khi);
    cudaGetSymbolAddress(&pkl, g_klo);
    cudaGetSymbolAddress(&pvf, g_vf);
    cudaGetSymbolAddress(&pat, g_att);

    __half* i3h = (__half*)pi3h;
    __half* i3l = (__half*)pi3l;
    __half* w4h = (__half*)pw4h;
    const size_t IS = (size_t)BLROWS * DMODEL;
    const size_t WS = (size_t)DMODEL * DMODEL;

    cudaFuncSetAttribute(gemm_qk, cudaFuncAttributeMaxDynamicSharedMemorySize, SMEM_GEMM);
    cudaFuncSetAttribute(gemm_v,  cudaFuncAttributeMaxDynamicSharedMemorySize, SMEM_GEMM);
    cudaFuncSetAttribute(gemm_wo, cudaFuncAttributeMaxDynamicSharedMemorySize, SMEM_GEMM);
    cudaFuncSetAttribute(attn_tc, cudaFuncAttributeMaxDynamicSharedMemorySize, SMEM_ATT);

    const int n4 = (BLROWS * DMODEL) / 4;
    const dim3 tb(32, 8);

    split3<<<dim3((n4 / 4 + 255) / 256, 1, 3), 256>>>(q, k, v, i3h, i3l, n4);
    splitT4<<<dim3(32, 32, 4), tb>>>(Wq, Wk, Wv, Wo, w4h);

    gemm_qk<<<dim3(DMODEL / 128, BLROWS / 128, 2), GEMM_THREADS, SMEM_GEMM>>>(
        i3h, i3l, w4h,
        (__nv_bfloat16*)pqh, (__nv_bfloat16*)pql,
        (__nv_bfloat16*)pkh, (__nv_bfloat16*)pkl);
    gemm_v<<<dim3(DMODEL / 128, BLROWS / 128), GEMM_THREADS, SMEM_GEMM>>>(
        i3h + 2 * IS, w4h + 2 * WS, (__half*)pvf);

    attn_tc<<<dim3(NHEAD * BATCH, SEQL / 128, 1), 256, SMEM_ATT>>>(
        (const __nv_bfloat16*)pqh, (const __nv_bfloat16*)pql,
        (const __nv_bfloat16*)pkh, (const __nv_bfloat16*)pkl,
        (const __half*)pvf, (__half*)pat);

    gemm_wo<<<dim3(DMODEL / 128, BLROWS / 128), GEMM_THREADS, SMEM_GEMM>>>(
        (const __half*)pat, w4h + 3 * WS, out);
}